// round 1
// baseline (speedup 1.0000x reference)
#include <cuda_runtime.h>
#include <math.h>

#define HW   65536
#define WIMG 256
#define C    384
#define C3   1152
#define NB   2

// Scratch (static device globals — allocation-free kernel_launch)
__device__ float g_qkv[(size_t)NB * C3 * HW];   // [b][3C][h*w]
__device__ float g_attn[(size_t)NB * C * HW];   // [b][C][h*w]

// ---------------------------------------------------------------------------
// GEMM: Out[b][m][n] = sum_k W[m][k] * X[b][k][n]
// BM=128, BN=64, BK=16, 256 threads, 8x4 register tile.
// Requires M%128==0, K%16==0, N%64==0 (true for all uses here).
// ---------------------------------------------------------------------------
__global__ __launch_bounds__(256) void gemm_wx(
    const float* __restrict__ Wt, const float* __restrict__ X,
    float* __restrict__ Out, int M, int K, int N)
{
    __shared__ float As[16 * 128]; // transposed: [k][m]
    __shared__ float Bs[16 * 64];  // [k][n]

    const int tid = threadIdx.x;
    const int tx = tid & 15;       // 16 n-groups of 4
    const int ty = tid >> 4;       // 16 m-groups of 8
    const int n0 = blockIdx.x * 64;
    const int m0 = blockIdx.y * 128;
    X   += (size_t)blockIdx.z * K * N;
    Out += (size_t)blockIdx.z * M * N;

    float acc[8][4];
    #pragma unroll
    for (int i = 0; i < 8; i++)
        #pragma unroll
        for (int j = 0; j < 4; j++) acc[i][j] = 0.f;

    for (int kt = 0; kt < K; kt += 16) {
        // Load A tile (128x16) transposed into As[k][m]
        #pragma unroll
        for (int l = 0; l < 2; ++l) {
            int lin = tid + l * 256;       // float4 index in tile
            int ml = lin >> 2, q = lin & 3;
            float4 w = *(const float4*)&Wt[(size_t)(m0 + ml) * K + kt + q * 4];
            As[(q * 4 + 0) * 128 + ml] = w.x;
            As[(q * 4 + 1) * 128 + ml] = w.y;
            As[(q * 4 + 2) * 128 + ml] = w.z;
            As[(q * 4 + 3) * 128 + ml] = w.w;
        }
        // Load B tile (16x64)
        {
            int kr = tid >> 4, q = tid & 15;
            *(float4*)&Bs[kr * 64 + q * 4] =
                *(const float4*)&X[(size_t)(kt + kr) * N + n0 + q * 4];
        }
        __syncthreads();

        #pragma unroll
        for (int kk = 0; kk < 16; ++kk) {
            float4 b4 = *(float4*)&Bs[kk * 64 + tx * 4];
            float4 a0 = *(float4*)&As[kk * 128 + ty * 8];
            float4 a1 = *(float4*)&As[kk * 128 + ty * 8 + 4];
            float a[8] = {a0.x, a0.y, a0.z, a0.w, a1.x, a1.y, a1.z, a1.w};
            float bb[4] = {b4.x, b4.y, b4.z, b4.w};
            #pragma unroll
            for (int i = 0; i < 8; i++)
                #pragma unroll
                for (int j = 0; j < 4; j++)
                    acc[i][j] += a[i] * bb[j];
        }
        __syncthreads();
    }

    #pragma unroll
    for (int i = 0; i < 8; i++) {
        float4 v = make_float4(acc[i][0], acc[i][1], acc[i][2], acc[i][3]);
        *(float4*)&Out[(size_t)(m0 + ty * 8 + i) * N + n0 + tx * 4] = v;
    }
}

// ---------------------------------------------------------------------------
// Window attention: one block per (window, head).
// blockIdx.x = window (wy*32+wx), blockIdx.y = head, blockIdx.z = batch.
// 64 tokens x 48 dims. S = QK^T * scale -> softmax -> O = P V.
// ---------------------------------------------------------------------------
__global__ __launch_bounds__(256) void win_attn()
{
    __shared__ float Qt[48 * 64];  // [d][t]
    __shared__ float KV[64 * 48];  // phase 1: Kt[d][t]; phase 2: Vs[t][d]
    __shared__ float Ss[64 * 65];  // padded scores

    const int tid  = threadIdx.x;
    const int head = blockIdx.y;
    const int b    = blockIdx.z;
    const int wy   = blockIdx.x >> 5;
    const int wx   = blockIdx.x & 31;

    const size_t base = ((size_t)b * C3 + (size_t)head * 48) * HW
                      + (size_t)(wy * 8) * WIMG + wx * 8;
    const float* qg = g_qkv + base;
    const float* kg = qg + (size_t)C * HW;
    const float* vg = qg + (size_t)2 * C * HW;

    // Stage Q, K transposed: [d][t]
    #pragma unroll
    for (int it = 0; it < 12; ++it) {
        int idx = tid + it * 256;          // 3072 = 48*64
        int d = idx >> 6, t = idx & 63;
        size_t off = (size_t)d * HW + (size_t)(t >> 3) * WIMG + (t & 7);
        Qt[idx] = qg[off];
        KV[idx] = kg[off];                 // Kt[d][t]
    }
    __syncthreads();

    const int tx = tid & 15, ty = tid >> 4;

    // S = Q K^T (4x4 per thread), scaled
    {
        float s[4][4];
        #pragma unroll
        for (int i = 0; i < 4; i++)
            #pragma unroll
            for (int j = 0; j < 4; j++) s[i][j] = 0.f;
        #pragma unroll
        for (int d = 0; d < 48; ++d) {
            float4 q4 = *(float4*)&Qt[d * 64 + ty * 4];
            float4 k4 = *(float4*)&KV[d * 64 + tx * 4];
            float qa[4] = {q4.x, q4.y, q4.z, q4.w};
            float ka[4] = {k4.x, k4.y, k4.z, k4.w};
            #pragma unroll
            for (int i = 0; i < 4; i++)
                #pragma unroll
                for (int j = 0; j < 4; j++)
                    s[i][j] += qa[i] * ka[j];
        }
        const float scale = 0.14433756729740643f; // 48^-0.5
        #pragma unroll
        for (int i = 0; i < 4; i++)
            #pragma unroll
            for (int j = 0; j < 4; j++)
                Ss[(ty * 4 + i) * 65 + tx * 4 + j] = s[i][j] * scale;
    }
    __syncthreads();   // S complete; K reads done -> KV reusable

    // Stage V as Vs[t][d] while 64 threads run row softmax
    #pragma unroll
    for (int it = 0; it < 12; ++it) {
        int idx = tid + it * 256;
        int d = idx >> 6, t = idx & 63;
        size_t off = (size_t)d * HW + (size_t)(t >> 3) * WIMG + (t & 7);
        KV[t * 48 + d] = vg[off];
    }
    if (tid < 64) {
        float* row = &Ss[tid * 65];
        float mx = -1e30f;
        #pragma unroll
        for (int j = 0; j < 64; j++) mx = fmaxf(mx, row[j]);
        float sum = 0.f;
        #pragma unroll
        for (int j = 0; j < 64; j++) { float e = __expf(row[j] - mx); row[j] = e; sum += e; }
        float inv = 1.f / sum;
        #pragma unroll
        for (int j = 0; j < 64; j++) row[j] *= inv;
    }
    __syncthreads();

    // O = P V : thread covers i = ty*4+ii (4 rows), d = tx*3+dd (3 dims)
    float o[4][3];
    #pragma unroll
    for (int i = 0; i < 4; i++)
        #pragma unroll
        for (int j = 0; j < 3; j++) o[i][j] = 0.f;
    #pragma unroll
    for (int j = 0; j < 64; ++j) {
        float p[4], v[3];
        #pragma unroll
        for (int i = 0; i < 4; i++) p[i] = Ss[(ty * 4 + i) * 65 + j];
        #pragma unroll
        for (int dd = 0; dd < 3; dd++) v[dd] = KV[j * 48 + tx * 3 + dd];
        #pragma unroll
        for (int i = 0; i < 4; i++)
            #pragma unroll
            for (int dd = 0; dd < 3; dd++)
                o[i][dd] += p[i] * v[dd];
    }

    float* og = g_attn + ((size_t)b * C + (size_t)head * 48) * HW
              + (size_t)(wy * 8) * WIMG + wx * 8;
    #pragma unroll
    for (int i = 0; i < 4; i++) {
        int t = ty * 4 + i;
        #pragma unroll
        for (int dd = 0; dd < 3; dd++) {
            og[(size_t)(tx * 3 + dd) * HW + (size_t)(t >> 3) * WIMG + (t & 7)] = o[i][dd];
        }
    }
}

// ---------------------------------------------------------------------------
extern "C" void kernel_launch(void* const* d_in, const int* in_sizes, int n_in,
                              void* d_out, int out_size)
{
    const float* x     = (const float*)d_in[0];
    const float* wqkv  = (const float*)d_in[1];
    const float* wproj = (const float*)d_in[2];
    float* out = (float*)d_out;

    float *qkv, *attn;
    cudaGetSymbolAddress((void**)&qkv, g_qkv);
    cudaGetSymbolAddress((void**)&attn, g_attn);

    // 1) QKV projection: [1152x384] x [384x65536] per batch
    dim3 g1(HW / 64, C3 / 128, NB);
    gemm_wx<<<g1, 256>>>(wqkv, x, qkv, C3, C, HW);

    // 2) Window attention: 1024 windows x 8 heads x 2 batches
    dim3 g2(1024, 8, NB);
    win_attn<<<g2, 256>>>();

    // 3) Output projection: [384x384] x [384x65536] per batch
    dim3 g3(HW / 64, C / 128, NB);
    gemm_wx<<<g3, 256>>>(wproj, attn, out, C, C, HW);
}

// round 3
// speedup vs baseline: 2.0574x; 2.0574x over previous
#include <cuda_runtime.h>
#include <math.h>

#define HW   65536
#define WIMG 256
#define C    384
#define C3   1152
#define NB   2

// Scratch (static device globals — allocation-free kernel_launch)
__device__ float g_qkv[(size_t)NB * C3 * HW];   // [b][3C][h*w]
__device__ float g_attn[(size_t)NB * C * HW];   // [b][C][h*w]

// ---------------------------------------------------------------------------
// TF32 helpers
// ---------------------------------------------------------------------------
__device__ __forceinline__ float to_tf32(float x) {
    float r;
    asm("cvt.rna.tf32.f32 %0, %1;" : "=f"(r) : "f"(x));
    return r;
}

__device__ __forceinline__ void mma_tf32(float c[4], const float a[4], const float b[2]) {
    asm volatile(
        "mma.sync.aligned.m16n8k8.row.col.f32.tf32.tf32.f32 "
        "{%0,%1,%2,%3}, {%4,%5,%6,%7}, {%8,%9}, {%0,%1,%2,%3};"
        : "+f"(c[0]), "+f"(c[1]), "+f"(c[2]), "+f"(c[3])
        : "r"(__float_as_uint(a[0])), "r"(__float_as_uint(a[1])),
          "r"(__float_as_uint(a[2])), "r"(__float_as_uint(a[3])),
          "r"(__float_as_uint(b[0])), "r"(__float_as_uint(b[1])));
}

// ---------------------------------------------------------------------------
// TF32 tensor-core GEMM: Out[b][m][n] = sum_k W[m][k] * X[b][k][n]
// BM=128, BN=128, BK=16. 256 threads = 8 warps (2 m x 4 n), warp tile 64x32.
// Requires M%128==0, K%16==0, N%128==0.
// ---------------------------------------------------------------------------
#define ASTR 20    // As row stride (16 + 4 pad): conflict-free fragment reads
#define BSTR 136   // Bs row stride (128 + 8 pad)

__global__ __launch_bounds__(256) void gemm_tf32(
    const float* __restrict__ Wt, const float* __restrict__ X,
    float* __restrict__ Out, int M, int K, int N)
{
    __shared__ float As[128 * ASTR];
    __shared__ float Bs[16 * BSTR];

    const int tid  = threadIdx.x;
    const int lane = tid & 31;
    const int wid  = tid >> 5;
    const int wm   = wid >> 2;       // 0..1
    const int wn   = wid & 3;        // 0..3
    const int n0   = blockIdx.x * 128;
    const int m0   = blockIdx.y * 128;
    X   += (size_t)blockIdx.z * K * N;
    Out += (size_t)blockIdx.z * M * N;

    float acc[4][4][4];
    #pragma unroll
    for (int i = 0; i < 4; i++)
        #pragma unroll
        for (int j = 0; j < 4; j++)
            #pragma unroll
            for (int v = 0; v < 4; v++) acc[i][j][v] = 0.f;

    // staging register buffers (prefetch)
    float4 ra[2], rb[2];

    // indices for staging
    const int am = tid >> 1;               // A: row m (0..127)
    const int aq = (tid & 1) * 2;          // A: float4 pair start (q, q+1)
    const int bk = tid >> 5;               // B: row k (0..7) (+8 with second)
    const int bc = (tid & 31) * 4;         // B: col

    // prologue: load first tile
    {
        ra[0] = *(const float4*)&Wt[(size_t)(m0 + am) * K + aq * 4];
        ra[1] = *(const float4*)&Wt[(size_t)(m0 + am) * K + (aq + 1) * 4];
        rb[0] = *(const float4*)&X[(size_t)bk * N + n0 + bc];
        rb[1] = *(const float4*)&X[(size_t)(bk + 8) * N + n0 + bc];
    }

    for (int kt = 0; kt < K; kt += 16) {
        // store staged tile to smem (tf32-rounded)
        {
            float* a0 = &As[am * ASTR + aq * 4];
            a0[0] = to_tf32(ra[0].x); a0[1] = to_tf32(ra[0].y);
            a0[2] = to_tf32(ra[0].z); a0[3] = to_tf32(ra[0].w);
            a0[4] = to_tf32(ra[1].x); a0[5] = to_tf32(ra[1].y);
            a0[6] = to_tf32(ra[1].z); a0[7] = to_tf32(ra[1].w);
            float* b0 = &Bs[bk * BSTR + bc];
            b0[0] = to_tf32(rb[0].x); b0[1] = to_tf32(rb[0].y);
            b0[2] = to_tf32(rb[0].z); b0[3] = to_tf32(rb[0].w);
            float* b1 = &Bs[(bk + 8) * BSTR + bc];
            b1[0] = to_tf32(rb[1].x); b1[1] = to_tf32(rb[1].y);
            b1[2] = to_tf32(rb[1].z); b1[3] = to_tf32(rb[1].w);
        }
        __syncthreads();

        // prefetch next tile
        if (kt + 16 < K) {
            ra[0] = *(const float4*)&Wt[(size_t)(m0 + am) * K + kt + 16 + aq * 4];
            ra[1] = *(const float4*)&Wt[(size_t)(m0 + am) * K + kt + 16 + (aq + 1) * 4];
            rb[0] = *(const float4*)&X[(size_t)(kt + 16 + bk) * N + n0 + bc];
            rb[1] = *(const float4*)&X[(size_t)(kt + 16 + bk + 8) * N + n0 + bc];
        }

        // compute: 2 k8 steps
        #pragma unroll
        for (int ks = 0; ks < 2; ++ks) {
            const int kk = ks * 8;
            float a[4][4], b[4][2];
            #pragma unroll
            for (int ma = 0; ma < 4; ++ma) {
                int r0 = wm * 64 + ma * 16 + (lane >> 2);
                int cc = kk + (lane & 3);
                a[ma][0] = As[r0 * ASTR + cc];
                a[ma][1] = As[(r0 + 8) * ASTR + cc];
                a[ma][2] = As[r0 * ASTR + cc + 4];
                a[ma][3] = As[(r0 + 8) * ASTR + cc + 4];
            }
            #pragma unroll
            for (int nb = 0; nb < 4; ++nb) {
                int cn = wn * 32 + nb * 8 + (lane >> 2);
                b[nb][0] = Bs[(kk + (lane & 3)) * BSTR + cn];
                b[nb][1] = Bs[(kk + 4 + (lane & 3)) * BSTR + cn];
            }
            #pragma unroll
            for (int ma = 0; ma < 4; ++ma)
                #pragma unroll
                for (int nb = 0; nb < 4; ++nb)
                    mma_tf32(acc[ma][nb], a[ma], b[nb]);
        }
        __syncthreads();
    }

    // epilogue: C fragment (m16n8): c0,c1 -> (lane/4, (lane%4)*2 +0,1); c2,c3 -> +8 rows
    #pragma unroll
    for (int ma = 0; ma < 4; ++ma) {
        #pragma unroll
        for (int nb = 0; nb < 4; ++nb) {
            int r = m0 + wm * 64 + ma * 16 + (lane >> 2);
            int cc = n0 + wn * 32 + nb * 8 + (lane & 3) * 2;
            float2 v0 = make_float2(acc[ma][nb][0], acc[ma][nb][1]);
            float2 v1 = make_float2(acc[ma][nb][2], acc[ma][nb][3]);
            *(float2*)&Out[(size_t)r * N + cc] = v0;
            *(float2*)&Out[(size_t)(r + 8) * N + cc] = v1;
        }
    }
}

// ---------------------------------------------------------------------------
// Window attention: one block per (window, head). (unchanged, fp32)
// ---------------------------------------------------------------------------
__global__ __launch_bounds__(256) void win_attn()
{
    __shared__ float Qt[48 * 64];  // [d][t]
    __shared__ float KV[64 * 48];  // phase 1: Kt[d][t]; phase 2: Vs[t][d]
    __shared__ float Ss[64 * 65];  // padded scores

    const int tid  = threadIdx.x;
    const int head = blockIdx.y;
    const int b    = blockIdx.z;
    const int wy   = blockIdx.x >> 5;
    const int wx   = blockIdx.x & 31;

    const size_t base = ((size_t)b * C3 + (size_t)head * 48) * HW
                      + (size_t)(wy * 8) * WIMG + wx * 8;
    const float* qg = g_qkv + base;
    const float* kg = qg + (size_t)C * HW;
    const float* vg = qg + (size_t)2 * C * HW;

    #pragma unroll
    for (int it = 0; it < 12; ++it) {
        int idx = tid + it * 256;
        int d = idx >> 6, t = idx & 63;
        size_t off = (size_t)d * HW + (size_t)(t >> 3) * WIMG + (t & 7);
        Qt[idx] = qg[off];
        KV[idx] = kg[off];
    }
    __syncthreads();

    const int tx = tid & 15, ty = tid >> 4;

    {
        float s[4][4];
        #pragma unroll
        for (int i = 0; i < 4; i++)
            #pragma unroll
            for (int j = 0; j < 4; j++) s[i][j] = 0.f;
        #pragma unroll
        for (int d = 0; d < 48; ++d) {
            float4 q4 = *(float4*)&Qt[d * 64 + ty * 4];
            float4 k4 = *(float4*)&KV[d * 64 + tx * 4];
            float qa[4] = {q4.x, q4.y, q4.z, q4.w};
            float ka[4] = {k4.x, k4.y, k4.z, k4.w};
            #pragma unroll
            for (int i = 0; i < 4; i++)
                #pragma unroll
                for (int j = 0; j < 4; j++)
                    s[i][j] += qa[i] * ka[j];
        }
        const float scale = 0.14433756729740643f;
        #pragma unroll
        for (int i = 0; i < 4; i++)
            #pragma unroll
            for (int j = 0; j < 4; j++)
                Ss[(ty * 4 + i) * 65 + tx * 4 + j] = s[i][j] * scale;
    }
    __syncthreads();

    #pragma unroll
    for (int it = 0; it < 12; ++it) {
        int idx = tid + it * 256;
        int d = idx >> 6, t = idx & 63;
        size_t off = (size_t)d * HW + (size_t)(t >> 3) * WIMG + (t & 7);
        KV[t * 48 + d] = vg[off];
    }
    if (tid < 64) {
        float* row = &Ss[tid * 65];
        float mx = -1e30f;
        #pragma unroll
        for (int j = 0; j < 64; j++) mx = fmaxf(mx, row[j]);
        float sum = 0.f;
        #pragma unroll
        for (int j = 0; j < 64; j++) { float e = __expf(row[j] - mx); row[j] = e; sum += e; }
        float inv = 1.f / sum;
        #pragma unroll
        for (int j = 0; j < 64; j++) row[j] *= inv;
    }
    __syncthreads();

    float o[4][3];
    #pragma unroll
    for (int i = 0; i < 4; i++)
        #pragma unroll
        for (int j = 0; j < 3; j++) o[i][j] = 0.f;
    #pragma unroll
    for (int j = 0; j < 64; ++j) {
        float p[4], v[3];
        #pragma unroll
        for (int i = 0; i < 4; i++) p[i] = Ss[(ty * 4 + i) * 65 + j];
        #pragma unroll
        for (int dd = 0; dd < 3; dd++) v[dd] = KV[j * 48 + tx * 3 + dd];
        #pragma unroll
        for (int i = 0; i < 4; i++)
            #pragma unroll
            for (int dd = 0; dd < 3; dd++)
                o[i][dd] += p[i] * v[dd];
    }

    float* og = g_attn + ((size_t)b * C + (size_t)head * 48) * HW
              + (size_t)(wy * 8) * WIMG + wx * 8;
    #pragma unroll
    for (int i = 0; i < 4; i++) {
        int t = ty * 4 + i;
        #pragma unroll
        for (int dd = 0; dd < 3; dd++) {
            og[(size_t)(tx * 3 + dd) * HW + (size_t)(t >> 3) * WIMG + (t & 7)] = o[i][dd];
        }
    }
}

// ---------------------------------------------------------------------------
extern "C" void kernel_launch(void* const* d_in, const int* in_sizes, int n_in,
                              void* d_out, int out_size)
{
    const float* x     = (const float*)d_in[0];
    const float* wqkv  = (const float*)d_in[1];
    const float* wproj = (const float*)d_in[2];
    float* out = (float*)d_out;

    float *qkv, *attn;
    cudaGetSymbolAddress((void**)&qkv, g_qkv);
    cudaGetSymbolAddress((void**)&attn, g_attn);

    // 1) QKV projection: [1152x384] x [384x65536] per batch
    dim3 g1(HW / 128, C3 / 128, NB);
    gemm_tf32<<<g1, 256>>>(wqkv, x, qkv, C3, C, HW);

    // 2) Window attention: 1024 windows x 8 heads x 2 batches
    dim3 g2(1024, 8, NB);
    win_attn<<<g2, 256>>>();

    // 3) Output projection: [384x384] x [384x65536] per batch
    dim3 g3(HW / 128, C / 128, NB);
    gemm_tf32<<<g3, 256>>>(wproj, attn, out, C, C, HW);
}

// round 5
// speedup vs baseline: 2.1997x; 1.0692x over previous
#include <cuda_runtime.h>
#include <cstdint>
#include <math.h>

#define HW   65536
#define WIMG 256
#define C    384
#define C3   1152
#define NB   2

// Scratch (static device globals — allocation-free kernel_launch)
__device__ float g_qkv[(size_t)NB * C3 * HW];   // [b][3C][h*w]
__device__ float g_attn[(size_t)NB * C * HW];   // [b][C][h*w]

// ---------------------------------------------------------------------------
// TF32 helpers
// ---------------------------------------------------------------------------
__device__ __forceinline__ float to_tf32(float x) {
    float r;
    asm("cvt.rna.tf32.f32 %0, %1;" : "=f"(r) : "f"(x));
    return r;
}

__device__ __forceinline__ void mma_tf32(float c[4], const float a[4], const float b[2]) {
    asm volatile(
        "mma.sync.aligned.m16n8k8.row.col.f32.tf32.tf32.f32 "
        "{%0,%1,%2,%3}, {%4,%5,%6,%7}, {%8,%9}, {%0,%1,%2,%3};"
        : "+f"(c[0]), "+f"(c[1]), "+f"(c[2]), "+f"(c[3])
        : "r"(__float_as_uint(a[0])), "r"(__float_as_uint(a[1])),
          "r"(__float_as_uint(a[2])), "r"(__float_as_uint(a[3])),
          "r"(__float_as_uint(b[0])), "r"(__float_as_uint(b[1])));
}

// ---------------------------------------------------------------------------
// TF32 tensor-core GEMM: Out[b][m][n] = sum_k W[m][k] * X[b][k][n]
// BM=128, BN=256, BK=16. 256 threads = 8 warps (2 m x 4 n), warp tile 64x64.
// Double-buffered smem, ONE __syncthreads per k-tile.
// Requires M%128==0, K%16==0, N%256==0.
// ---------------------------------------------------------------------------
#define ASTR 20    // As row stride (16 + 4 pad): conflict-free fragment reads
#define BSTR 264   // Bs row stride (256 + 8 pad)
#define ABYTES (128 * ASTR * 4)     // 10240
#define BBYTES (16 * BSTR * 4)      // 16896
#define BUFBYTES (ABYTES + BBYTES)  // 27136

__global__ __launch_bounds__(256, 1) void gemm_tf32(
    const float* __restrict__ Wt, const float* __restrict__ X,
    float* __restrict__ Out, int M, int K, int N)
{
    extern __shared__ float sm[];

    const int tid  = threadIdx.x;
    const int lane = tid & 31;
    const int wid  = tid >> 5;
    const int wm   = wid >> 2;       // 0..1
    const int wn   = wid & 3;        // 0..3
    const int n0   = blockIdx.x * 256;
    const int m0   = blockIdx.y * 128;
    X   += (size_t)blockIdx.z * K * N;
    Out += (size_t)blockIdx.z * M * N;

    float acc[4][8][4];
    #pragma unroll
    for (int i = 0; i < 4; i++)
        #pragma unroll
        for (int j = 0; j < 8; j++)
            #pragma unroll
            for (int v = 0; v < 4; v++) acc[i][j][v] = 0.f;

    // staging indices
    const int am = tid >> 1;               // A row m (0..127)
    const int aq = (tid & 1) * 2;          // A float4 pair (k-quads aq, aq+1)
    const int bk = tid >> 6;               // B base row k (0..3), rows bk+4i
    const int bc = (tid & 63) * 4;         // B col

    float4 ra[2], rb[4];

    // prologue: load first tile
    ra[0] = *(const float4*)&Wt[(size_t)(m0 + am) * K + aq * 4];
    ra[1] = *(const float4*)&Wt[(size_t)(m0 + am) * K + (aq + 1) * 4];
    #pragma unroll
    for (int i = 0; i < 4; ++i)
        rb[i] = *(const float4*)&X[(size_t)(bk + i * 4) * N + n0 + bc];

    const int ntile = K / 16;
    for (int t = 0; t < ntile; ++t) {
        float* As = sm + (t & 1) * (BUFBYTES / 4);
        float* Bs = As + ABYTES / 4;

        // store staged tile (tf32-rounded)
        {
            float* a0 = &As[am * ASTR + aq * 4];
            a0[0] = to_tf32(ra[0].x); a0[1] = to_tf32(ra[0].y);
            a0[2] = to_tf32(ra[0].z); a0[3] = to_tf32(ra[0].w);
            a0[4] = to_tf32(ra[1].x); a0[5] = to_tf32(ra[1].y);
            a0[6] = to_tf32(ra[1].z); a0[7] = to_tf32(ra[1].w);
            #pragma unroll
            for (int i = 0; i < 4; ++i) {
                float* b0 = &Bs[(bk + i * 4) * BSTR + bc];
                b0[0] = to_tf32(rb[i].x); b0[1] = to_tf32(rb[i].y);
                b0[2] = to_tf32(rb[i].z); b0[3] = to_tf32(rb[i].w);
            }
        }
        __syncthreads();

        // prefetch next tile
        if (t + 1 < ntile) {
            const int kt = (t + 1) * 16;
            ra[0] = *(const float4*)&Wt[(size_t)(m0 + am) * K + kt + aq * 4];
            ra[1] = *(const float4*)&Wt[(size_t)(m0 + am) * K + kt + (aq + 1) * 4];
            #pragma unroll
            for (int i = 0; i < 4; ++i)
                rb[i] = *(const float4*)&X[(size_t)(kt + bk + i * 4) * N + n0 + bc];
        }

        // compute: 2 k8 steps, warp tile 64x64
        #pragma unroll
        for (int ks = 0; ks < 2; ++ks) {
            const int kk = ks * 8;
            float a[4][4], b[8][2];
            #pragma unroll
            for (int ma = 0; ma < 4; ++ma) {
                int r0 = wm * 64 + ma * 16 + (lane >> 2);
                int cc = kk + (lane & 3);
                a[ma][0] = As[r0 * ASTR + cc];
                a[ma][1] = As[(r0 + 8) * ASTR + cc];
                a[ma][2] = As[r0 * ASTR + cc + 4];
                a[ma][3] = As[(r0 + 8) * ASTR + cc + 4];
            }
            #pragma unroll
            for (int nb = 0; nb < 8; ++nb) {
                int cn = wn * 64 + nb * 8 + (lane >> 2);
                b[nb][0] = Bs[(kk + (lane & 3)) * BSTR + cn];
                b[nb][1] = Bs[(kk + 4 + (lane & 3)) * BSTR + cn];
            }
            #pragma unroll
            for (int ma = 0; ma < 4; ++ma)
                #pragma unroll
                for (int nb = 0; nb < 8; ++nb)
                    mma_tf32(acc[ma][nb], a[ma], b[nb]);
        }
        // NOTE: single barrier per tile is sufficient with 2 buffers:
        // passing the sync at iter t implies all warps finished compute t-1,
        // and iter t+1 stores to the other buffer.
    }

    // epilogue
    #pragma unroll
    for (int ma = 0; ma < 4; ++ma) {
        #pragma unroll
        for (int nb = 0; nb < 8; ++nb) {
            int r  = m0 + wm * 64 + ma * 16 + (lane >> 2);
            int cc = n0 + wn * 64 + nb * 8 + (lane & 3) * 2;
            *(float2*)&Out[(size_t)r * N + cc] =
                make_float2(acc[ma][nb][0], acc[ma][nb][1]);
            *(float2*)&Out[(size_t)(r + 8) * N + cc] =
                make_float2(acc[ma][nb][2], acc[ma][nb][3]);
        }
    }
}

// ---------------------------------------------------------------------------
// Window attention: one block per (window, head). (fp32, unchanged)
// ---------------------------------------------------------------------------
__global__ __launch_bounds__(256) void win_attn()
{
    __shared__ float Qt[48 * 64];  // [d][t]
    __shared__ float KV[64 * 48];  // phase 1: Kt[d][t]; phase 2: Vs[t][d]
    __shared__ float Ss[64 * 65];  // padded scores

    const int tid  = threadIdx.x;
    const int head = blockIdx.y;
    const int b    = blockIdx.z;
    const int wy   = blockIdx.x >> 5;
    const int wx   = blockIdx.x & 31;

    const size_t base = ((size_t)b * C3 + (size_t)head * 48) * HW
                      + (size_t)(wy * 8) * WIMG + wx * 8;
    const float* qg = g_qkv + base;
    const float* kg = qg + (size_t)C * HW;
    const float* vg = qg + (size_t)2 * C * HW;

    #pragma unroll
    for (int it = 0; it < 12; ++it) {
        int idx = tid + it * 256;
        int d = idx >> 6, t = idx & 63;
        size_t off = (size_t)d * HW + (size_t)(t >> 3) * WIMG + (t & 7);
        Qt[idx] = qg[off];
        KV[idx] = kg[off];
    }
    __syncthreads();

    const int tx = tid & 15, ty = tid >> 4;

    {
        float s[4][4];
        #pragma unroll
        for (int i = 0; i < 4; i++)
            #pragma unroll
            for (int j = 0; j < 4; j++) s[i][j] = 0.f;
        #pragma unroll
        for (int d = 0; d < 48; ++d) {
            float4 q4 = *(float4*)&Qt[d * 64 + ty * 4];
            float4 k4 = *(float4*)&KV[d * 64 + tx * 4];
            float qa[4] = {q4.x, q4.y, q4.z, q4.w};
            float ka[4] = {k4.x, k4.y, k4.z, k4.w};
            #pragma unroll
            for (int i = 0; i < 4; i++)
                #pragma unroll
                for (int j = 0; j < 4; j++)
                    s[i][j] += qa[i] * ka[j];
        }
        const float scale = 0.14433756729740643f;
        #pragma unroll
        for (int i = 0; i < 4; i++)
            #pragma unroll
            for (int j = 0; j < 4; j++)
                Ss[(ty * 4 + i) * 65 + tx * 4 + j] = s[i][j] * scale;
    }
    __syncthreads();

    #pragma unroll
    for (int it = 0; it < 12; ++it) {
        int idx = tid + it * 256;
        int d = idx >> 6, t = idx & 63;
        size_t off = (size_t)d * HW + (size_t)(t >> 3) * WIMG + (t & 7);
        KV[t * 48 + d] = vg[off];
    }
    if (tid < 64) {
        float* row = &Ss[tid * 65];
        float mx = -1e30f;
        #pragma unroll
        for (int j = 0; j < 64; j++) mx = fmaxf(mx, row[j]);
        float sum = 0.f;
        #pragma unroll
        for (int j = 0; j < 64; j++) { float e = __expf(row[j] - mx); row[j] = e; sum += e; }
        float inv = 1.f / sum;
        #pragma unroll
        for (int j = 0; j < 64; j++) row[j] *= inv;
    }
    __syncthreads();

    float o[4][3];
    #pragma unroll
    for (int i = 0; i < 4; i++)
        #pragma unroll
        for (int j = 0; j < 3; j++) o[i][j] = 0.f;
    #pragma unroll
    for (int j = 0; j < 64; ++j) {
        float p[4], v[3];
        #pragma unroll
        for (int i = 0; i < 4; i++) p[i] = Ss[(ty * 4 + i) * 65 + j];
        #pragma unroll
        for (int dd = 0; dd < 3; dd++) v[dd] = KV[j * 48 + tx * 3 + dd];
        #pragma unroll
        for (int i = 0; i < 4; i++)
            #pragma unroll
            for (int dd = 0; dd < 3; dd++)
                o[i][dd] += p[i] * v[dd];
    }

    float* og = g_attn + ((size_t)b * C + (size_t)head * 48) * HW
              + (size_t)(wy * 8) * WIMG + wx * 8;
    #pragma unroll
    for (int i = 0; i < 4; i++) {
        int t = ty * 4 + i;
        #pragma unroll
        for (int dd = 0; dd < 3; dd++) {
            og[(size_t)(tx * 3 + dd) * HW + (size_t)(t >> 3) * WIMG + (t & 7)] = o[i][dd];
        }
    }
}

// ---------------------------------------------------------------------------
extern "C" void kernel_launch(void* const* d_in, const int* in_sizes, int n_in,
                              void* d_out, int out_size)
{
    const float* x     = (const float*)d_in[0];
    const float* wqkv  = (const float*)d_in[1];
    const float* wproj = (const float*)d_in[2];
    float* out = (float*)d_out;

    float *qkv, *attn;
    cudaGetSymbolAddress((void**)&qkv, g_qkv);
    cudaGetSymbolAddress((void**)&attn, g_attn);

    const int smem_bytes = 2 * BUFBYTES;   // 54272
    cudaFuncSetAttribute(gemm_tf32, cudaFuncAttributeMaxDynamicSharedMemorySize, smem_bytes);

    // 1) QKV projection: [1152x384] x [384x65536] per batch
    dim3 g1(HW / 256, C3 / 128, NB);
    gemm_tf32<<<g1, 256, smem_bytes>>>(wqkv, x, qkv, C3, C, HW);

    // 2) Window attention: 1024 windows x 8 heads x 2 batches
    dim3 g2(1024, 8, NB);
    win_attn<<<g2, 256>>>();

    // 3) Output projection: [384x384] x [384x65536] per batch
    dim3 g3(HW / 256, C / 128, NB);
    gemm_tf32<<<g3, 256, smem_bytes>>>(wproj, attn, out, C, C, HW);
}

// round 6
// speedup vs baseline: 2.6132x; 1.1880x over previous
#include <cuda_runtime.h>
#include <cstdint>
#include <math.h>

#define HW   65536
#define WIMG 256
#define C    384
#define C3   1152
#define NB   2

// Scratch (static device globals — allocation-free kernel_launch)
__device__ float g_qkv[(size_t)NB * C3 * HW];   // [b][3C][h*w]
__device__ float g_attn[(size_t)NB * C * HW];   // [b][C][h*w]

// ---------------------------------------------------------------------------
// TF32 helpers
// ---------------------------------------------------------------------------
__device__ __forceinline__ float to_tf32(float x) {
    float r;
    asm("cvt.rna.tf32.f32 %0, %1;" : "=f"(r) : "f"(x));
    return r;
}

__device__ __forceinline__ void mma_tf32(float c[4], const float a[4], const float b[2]) {
    asm volatile(
        "mma.sync.aligned.m16n8k8.row.col.f32.tf32.tf32.f32 "
        "{%0,%1,%2,%3}, {%4,%5,%6,%7}, {%8,%9}, {%0,%1,%2,%3};"
        : "+f"(c[0]), "+f"(c[1]), "+f"(c[2]), "+f"(c[3])
        : "r"(__float_as_uint(a[0])), "r"(__float_as_uint(a[1])),
          "r"(__float_as_uint(a[2])), "r"(__float_as_uint(a[3])),
          "r"(__float_as_uint(b[0])), "r"(__float_as_uint(b[1])));
}

// ---------------------------------------------------------------------------
// TF32 tensor-core GEMM (unchanged from R5 — proven at 41.6% tensor)
// BM=128, BN=256, BK=16. 256 threads = 8 warps (2 m x 4 n), warp tile 64x64.
// ---------------------------------------------------------------------------
#define ASTR 20
#define BSTR 264
#define ABYTES (128 * ASTR * 4)
#define BBYTES (16 * BSTR * 4)
#define BUFBYTES (ABYTES + BBYTES)

__global__ __launch_bounds__(256, 1) void gemm_tf32(
    const float* __restrict__ Wt, const float* __restrict__ X,
    float* __restrict__ Out, int M, int K, int N)
{
    extern __shared__ float sm[];

    const int tid  = threadIdx.x;
    const int lane = tid & 31;
    const int wid  = tid >> 5;
    const int wm   = wid >> 2;
    const int wn   = wid & 3;
    const int n0   = blockIdx.x * 256;
    const int m0   = blockIdx.y * 128;
    X   += (size_t)blockIdx.z * K * N;
    Out += (size_t)blockIdx.z * M * N;

    float acc[4][8][4];
    #pragma unroll
    for (int i = 0; i < 4; i++)
        #pragma unroll
        for (int j = 0; j < 8; j++)
            #pragma unroll
            for (int v = 0; v < 4; v++) acc[i][j][v] = 0.f;

    const int am = tid >> 1;
    const int aq = (tid & 1) * 2;
    const int bk = tid >> 6;
    const int bc = (tid & 63) * 4;

    float4 ra[2], rb[4];

    ra[0] = *(const float4*)&Wt[(size_t)(m0 + am) * K + aq * 4];
    ra[1] = *(const float4*)&Wt[(size_t)(m0 + am) * K + (aq + 1) * 4];
    #pragma unroll
    for (int i = 0; i < 4; ++i)
        rb[i] = *(const float4*)&X[(size_t)(bk + i * 4) * N + n0 + bc];

    const int ntile = K / 16;
    for (int t = 0; t < ntile; ++t) {
        float* As = sm + (t & 1) * (BUFBYTES / 4);
        float* Bs = As + ABYTES / 4;

        {
            float* a0 = &As[am * ASTR + aq * 4];
            a0[0] = to_tf32(ra[0].x); a0[1] = to_tf32(ra[0].y);
            a0[2] = to_tf32(ra[0].z); a0[3] = to_tf32(ra[0].w);
            a0[4] = to_tf32(ra[1].x); a0[5] = to_tf32(ra[1].y);
            a0[6] = to_tf32(ra[1].z); a0[7] = to_tf32(ra[1].w);
            #pragma unroll
            for (int i = 0; i < 4; ++i) {
                float* b0 = &Bs[(bk + i * 4) * BSTR + bc];
                b0[0] = to_tf32(rb[i].x); b0[1] = to_tf32(rb[i].y);
                b0[2] = to_tf32(rb[i].z); b0[3] = to_tf32(rb[i].w);
            }
        }
        __syncthreads();

        if (t + 1 < ntile) {
            const int kt = (t + 1) * 16;
            ra[0] = *(const float4*)&Wt[(size_t)(m0 + am) * K + kt + aq * 4];
            ra[1] = *(const float4*)&Wt[(size_t)(m0 + am) * K + kt + (aq + 1) * 4];
            #pragma unroll
            for (int i = 0; i < 4; ++i)
                rb[i] = *(const float4*)&X[(size_t)(kt + bk + i * 4) * N + n0 + bc];
        }

        #pragma unroll
        for (int ks = 0; ks < 2; ++ks) {
            const int kk = ks * 8;
            float a[4][4], b[8][2];
            #pragma unroll
            for (int ma = 0; ma < 4; ++ma) {
                int r0 = wm * 64 + ma * 16 + (lane >> 2);
                int cc = kk + (lane & 3);
                a[ma][0] = As[r0 * ASTR + cc];
                a[ma][1] = As[(r0 + 8) * ASTR + cc];
                a[ma][2] = As[r0 * ASTR + cc + 4];
                a[ma][3] = As[(r0 + 8) * ASTR + cc + 4];
            }
            #pragma unroll
            for (int nb = 0; nb < 8; ++nb) {
                int cn = wn * 64 + nb * 8 + (lane >> 2);
                b[nb][0] = Bs[(kk + (lane & 3)) * BSTR + cn];
                b[nb][1] = Bs[(kk + 4 + (lane & 3)) * BSTR + cn];
            }
            #pragma unroll
            for (int ma = 0; ma < 4; ++ma)
                #pragma unroll
                for (int nb = 0; nb < 8; ++nb)
                    mma_tf32(acc[ma][nb], a[ma], b[nb]);
        }
    }

    #pragma unroll
    for (int ma = 0; ma < 4; ++ma) {
        #pragma unroll
        for (int nb = 0; nb < 8; ++nb) {
            int r  = m0 + wm * 64 + ma * 16 + (lane >> 2);
            int cc = n0 + wn * 64 + nb * 8 + (lane & 3) * 2;
            *(float2*)&Out[(size_t)r * N + cc] =
                make_float2(acc[ma][nb][0], acc[ma][nb][1]);
            *(float2*)&Out[(size_t)(r + 8) * N + cc] =
                make_float2(acc[ma][nb][2], acc[ma][nb][3]);
        }
    }
}

// ---------------------------------------------------------------------------
// Window attention on TF32 mma.sync. Block = one (window, head), 128 threads.
// Warp w owns S-rows [16w, 16w+16). Softmax in registers (quad shfl).
// Smem: Qs[64][52], Ks[64][52], Vs[64][56], Ss[64][68] — 58368 B dynamic.
// ---------------------------------------------------------------------------
#define QSTR 52
#define VSTR 56
#define SSTR 68

__global__ __launch_bounds__(128) void win_attn()
{
    extern __shared__ float smw[];
    float* Qs = smw;                    // 64*52 = 3328
    float* Ks = smw + 3328;             // 64*52
    float* Vs = smw + 6656;             // 64*56 = 3584
    float* Ss = smw + 10240;            // 64*68 = 4352

    const int tid  = threadIdx.x;
    const int lane = tid & 31;
    const int wid  = tid >> 5;          // m-tile 0..3
    const int head = blockIdx.y;
    const int b    = blockIdx.z;
    const int wy   = blockIdx.x >> 5;
    const int wx   = blockIdx.x & 31;

    const size_t base = ((size_t)b * C3 + (size_t)head * 48) * HW
                      + (size_t)(wy * 8) * WIMG + wx * 8;
    const float* qg = g_qkv + base;
    const float* kg = qg + (size_t)C * HW;
    const float* vg = qg + (size_t)2 * C * HW;
    const float scale = 0.14433756729740643f;   // 48^-0.5

    // Stage Q*scale, K, V (tf32-rounded). [token][dim] layouts.
    #pragma unroll
    for (int it = 0; it < 24; ++it) {
        int idx = tid + it * 128;       // 3072 = 48*64
        int d = idx >> 6, t = idx & 63;
        size_t off = (size_t)d * HW + (size_t)(t >> 3) * WIMG + (t & 7);
        Qs[t * QSTR + d] = to_tf32(qg[off] * scale);
        Ks[t * QSTR + d] = to_tf32(kg[off]);
        Vs[t * VSTR + d] = to_tf32(vg[off]);
    }
    __syncthreads();

    const int r  = lane >> 2;           // 0..7
    const int cq = lane & 3;            // 0..3
    const int row0 = wid * 16 + r;

    // ---- S = Q K^T : warp strip 16x64, 8 n-tiles x 6 k8 ----
    float sacc[8][4];
    #pragma unroll
    for (int nb = 0; nb < 8; ++nb)
        #pragma unroll
        for (int v = 0; v < 4; ++v) sacc[nb][v] = 0.f;

    #pragma unroll
    for (int k8 = 0; k8 < 6; ++k8) {
        const int kk = k8 * 8;
        float a[4];
        a[0] = Qs[row0 * QSTR + kk + cq];
        a[1] = Qs[(row0 + 8) * QSTR + kk + cq];
        a[2] = Qs[row0 * QSTR + kk + cq + 4];
        a[3] = Qs[(row0 + 8) * QSTR + kk + cq + 4];
        #pragma unroll
        for (int nb = 0; nb < 8; ++nb) {
            const int cn = nb * 8 + r;
            float bb[2];
            bb[0] = Ks[cn * QSTR + kk + cq];
            bb[1] = Ks[cn * QSTR + kk + 4 + cq];
            mma_tf32(sacc[nb], a, bb);
        }
    }

    // ---- softmax in registers: row row0 -> (c0,c1), row0+8 -> (c2,c3) ----
    float mx0 = -1e30f, mx8 = -1e30f;
    #pragma unroll
    for (int nb = 0; nb < 8; ++nb) {
        mx0 = fmaxf(mx0, fmaxf(sacc[nb][0], sacc[nb][1]));
        mx8 = fmaxf(mx8, fmaxf(sacc[nb][2], sacc[nb][3]));
    }
    mx0 = fmaxf(mx0, __shfl_xor_sync(0xffffffffu, mx0, 1));
    mx0 = fmaxf(mx0, __shfl_xor_sync(0xffffffffu, mx0, 2));
    mx8 = fmaxf(mx8, __shfl_xor_sync(0xffffffffu, mx8, 1));
    mx8 = fmaxf(mx8, __shfl_xor_sync(0xffffffffu, mx8, 2));

    float s0 = 0.f, s8 = 0.f;
    #pragma unroll
    for (int nb = 0; nb < 8; ++nb) {
        sacc[nb][0] = __expf(sacc[nb][0] - mx0); s0 += sacc[nb][0];
        sacc[nb][1] = __expf(sacc[nb][1] - mx0); s0 += sacc[nb][1];
        sacc[nb][2] = __expf(sacc[nb][2] - mx8); s8 += sacc[nb][2];
        sacc[nb][3] = __expf(sacc[nb][3] - mx8); s8 += sacc[nb][3];
    }
    s0 += __shfl_xor_sync(0xffffffffu, s0, 1);
    s0 += __shfl_xor_sync(0xffffffffu, s0, 2);
    s8 += __shfl_xor_sync(0xffffffffu, s8, 1);
    s8 += __shfl_xor_sync(0xffffffffu, s8, 2);
    const float i0 = 1.f / s0, i8 = 1.f / s8;

    // store P (tf32-rounded) to own strip of Ss
    #pragma unroll
    for (int nb = 0; nb < 8; ++nb) {
        const int cb = nb * 8 + 2 * cq;
        Ss[row0 * SSTR + cb]           = to_tf32(sacc[nb][0] * i0);
        Ss[row0 * SSTR + cb + 1]       = to_tf32(sacc[nb][1] * i0);
        Ss[(row0 + 8) * SSTR + cb]     = to_tf32(sacc[nb][2] * i8);
        Ss[(row0 + 8) * SSTR + cb + 1] = to_tf32(sacc[nb][3] * i8);
    }
    __syncwarp();   // cross-lane STS -> LDS within the warp

    // ---- O = P V : strip 16x48, 6 n-tiles x 8 k8 ----
    float oacc[6][4];
    #pragma unroll
    for (int nb = 0; nb < 6; ++nb)
        #pragma unroll
        for (int v = 0; v < 4; ++v) oacc[nb][v] = 0.f;

    #pragma unroll
    for (int k8 = 0; k8 < 8; ++k8) {
        const int kk = k8 * 8;
        float a[4];
        a[0] = Ss[row0 * SSTR + kk + cq];
        a[1] = Ss[(row0 + 8) * SSTR + kk + cq];
        a[2] = Ss[row0 * SSTR + kk + cq + 4];
        a[3] = Ss[(row0 + 8) * SSTR + kk + cq + 4];
        #pragma unroll
        for (int nb = 0; nb < 6; ++nb) {
            const int cn = nb * 8 + r;
            float bb[2];
            bb[0] = Vs[(kk + cq) * VSTR + cn];
            bb[1] = Vs[(kk + 4 + cq) * VSTR + cn];
            mma_tf32(oacc[nb], a, bb);
        }
    }

    // ---- store O: (token t, dim d) -> g_attn[head*48+d][pix(t)] ----
    float* og = g_attn + ((size_t)b * C + (size_t)head * 48) * HW
              + (size_t)(wy * 8) * WIMG + wx * 8;
    const int t0 = row0, t8 = row0 + 8;
    const size_t p0 = (size_t)(t0 >> 3) * WIMG + (t0 & 7);
    const size_t p8 = (size_t)(t8 >> 3) * WIMG + (t8 & 7);
    #pragma unroll
    for (int nb = 0; nb < 6; ++nb) {
        const int d0 = nb * 8 + 2 * cq;
        og[(size_t)d0 * HW + p0]       = oacc[nb][0];
        og[(size_t)(d0 + 1) * HW + p0] = oacc[nb][1];
        og[(size_t)d0 * HW + p8]       = oacc[nb][2];
        og[(size_t)(d0 + 1) * HW + p8] = oacc[nb][3];
    }
}

// ---------------------------------------------------------------------------
extern "C" void kernel_launch(void* const* d_in, const int* in_sizes, int n_in,
                              void* d_out, int out_size)
{
    const float* x     = (const float*)d_in[0];
    const float* wqkv  = (const float*)d_in[1];
    const float* wproj = (const float*)d_in[2];
    float* out = (float*)d_out;

    float *qkv, *attn;
    cudaGetSymbolAddress((void**)&qkv, g_qkv);
    cudaGetSymbolAddress((void**)&attn, g_attn);

    const int smem_bytes = 2 * BUFBYTES;       // 54272
    const int attn_smem  = 14592 * 4;          // 58368
    cudaFuncSetAttribute(gemm_tf32, cudaFuncAttributeMaxDynamicSharedMemorySize, smem_bytes);
    cudaFuncSetAttribute(win_attn, cudaFuncAttributeMaxDynamicSharedMemorySize, attn_smem);

    // 1) QKV projection: [1152x384] x [384x65536] per batch
    dim3 g1(HW / 256, C3 / 128, NB);
    gemm_tf32<<<g1, 256, smem_bytes>>>(wqkv, x, qkv, C3, C, HW);

    // 2) Window attention: 1024 windows x 8 heads x 2 batches
    dim3 g2(1024, 8, NB);
    win_attn<<<g2, 128, attn_smem>>>();

    // 3) Output projection: [384x384] x [384x65536] per batch
    dim3 g3(HW / 256, C / 128, NB);
    gemm_tf32<<<g3, 256, smem_bytes>>>(wproj, attn, out, C, C, HW);
}

// round 8
// speedup vs baseline: 2.8434x; 1.0881x over previous
#include <cuda_runtime.h>
#include <cstdint>
#include <math.h>

#define HW   65536
#define WIMG 256
#define C    384
#define C3   1152
#define NB   2

// Scratch (static device globals — allocation-free kernel_launch)
__device__ float g_qkv[(size_t)NB * C3 * HW];   // [b][3C][h*w]
__device__ float g_attn[(size_t)NB * C * HW];   // [b][C][h*w]

// ---------------------------------------------------------------------------
// TF32 helpers
// ---------------------------------------------------------------------------
__device__ __forceinline__ float to_tf32(float x) {
    float r;
    asm("cvt.rna.tf32.f32 %0, %1;" : "=f"(r) : "f"(x));
    return r;
}

__device__ __forceinline__ void mma_tf32(float c[4], const float a[4], const float b[2]) {
    asm volatile(
        "mma.sync.aligned.m16n8k8.row.col.f32.tf32.tf32.f32 "
        "{%0,%1,%2,%3}, {%4,%5,%6,%7}, {%8,%9}, {%0,%1,%2,%3};"
        : "+f"(c[0]), "+f"(c[1]), "+f"(c[2]), "+f"(c[3])
        : "r"(__float_as_uint(a[0])), "r"(__float_as_uint(a[1])),
          "r"(__float_as_uint(a[2])), "r"(__float_as_uint(a[3])),
          "r"(__float_as_uint(b[0])), "r"(__float_as_uint(b[1])));
}

// ---------------------------------------------------------------------------
// TF32 tensor-core GEMM: Out[b][m][n] = sum_k W[m][k] * X[b][k][n]
// BM=128, BN=256, BK=16. 512 threads = 16 warps (2 m x 8 n), warp tile 64x32.
// Grid: blockIdx.x = m (fast) -> wave covers all m-blocks => X reuse in L2.
// Double-buffered smem, one __syncthreads per k-tile.
// ---------------------------------------------------------------------------
#define ASTR 20
#define BSTR 264
#define ABYTES (128 * ASTR * 4)        // 10240
#define BBYTES (16 * BSTR * 4)         // 16896
#define BUFBYTES (ABYTES + BBYTES)     // 27136

__global__ __launch_bounds__(512, 1) void gemm_tf32(
    const float* __restrict__ Wt, const float* __restrict__ X,
    float* __restrict__ Out, int M, int K, int N)
{
    extern __shared__ float sm[];

    const int tid  = threadIdx.x;
    const int lane = tid & 31;
    const int wid  = tid >> 5;
    const int wm   = wid >> 3;       // 0..1
    const int wn   = wid & 7;        // 0..7
    const int m0   = blockIdx.x * 128;
    const int n0   = blockIdx.y * 256;
    X   += (size_t)blockIdx.z * K * N;
    Out += (size_t)blockIdx.z * M * N;

    float acc[4][4][4];
    #pragma unroll
    for (int i = 0; i < 4; i++)
        #pragma unroll
        for (int j = 0; j < 4; j++)
            #pragma unroll
            for (int v = 0; v < 4; v++) acc[i][j][v] = 0.f;

    // staging indices (512 threads)
    const int am = tid >> 2;               // A row m (0..127)
    const int aq = tid & 3;                // A k-quad (0..3)
    const int bk = tid >> 6;               // B rows bk, bk+8 (0..7)
    const int bc = (tid & 63) * 4;         // B col

    float4 ra, rb[2];

    // prologue
    ra    = *(const float4*)&Wt[(size_t)(m0 + am) * K + aq * 4];
    rb[0] = *(const float4*)&X[(size_t)bk * N + n0 + bc];
    rb[1] = *(const float4*)&X[(size_t)(bk + 8) * N + n0 + bc];

    const int ntile = K / 16;
    for (int t = 0; t < ntile; ++t) {
        float* As = sm + (t & 1) * (BUFBYTES / 4);
        float* Bs = As + ABYTES / 4;

        {
            float* a0 = &As[am * ASTR + aq * 4];
            a0[0] = to_tf32(ra.x); a0[1] = to_tf32(ra.y);
            a0[2] = to_tf32(ra.z); a0[3] = to_tf32(ra.w);
            float* b0 = &Bs[bk * BSTR + bc];
            b0[0] = to_tf32(rb[0].x); b0[1] = to_tf32(rb[0].y);
            b0[2] = to_tf32(rb[0].z); b0[3] = to_tf32(rb[0].w);
            float* b1 = &Bs[(bk + 8) * BSTR + bc];
            b1[0] = to_tf32(rb[1].x); b1[1] = to_tf32(rb[1].y);
            b1[2] = to_tf32(rb[1].z); b1[3] = to_tf32(rb[1].w);
        }
        __syncthreads();

        if (t + 1 < ntile) {
            const int kt = (t + 1) * 16;
            ra    = *(const float4*)&Wt[(size_t)(m0 + am) * K + kt + aq * 4];
            rb[0] = *(const float4*)&X[(size_t)(kt + bk) * N + n0 + bc];
            rb[1] = *(const float4*)&X[(size_t)(kt + bk + 8) * N + n0 + bc];
        }

        #pragma unroll
        for (int ks = 0; ks < 2; ++ks) {
            const int kk = ks * 8;
            float a[4][4], b[4][2];
            #pragma unroll
            for (int ma = 0; ma < 4; ++ma) {
                int r0 = wm * 64 + ma * 16 + (lane >> 2);
                int cc = kk + (lane & 3);
                a[ma][0] = As[r0 * ASTR + cc];
                a[ma][1] = As[(r0 + 8) * ASTR + cc];
                a[ma][2] = As[r0 * ASTR + cc + 4];
                a[ma][3] = As[(r0 + 8) * ASTR + cc + 4];
            }
            #pragma unroll
            for (int nb = 0; nb < 4; ++nb) {
                int cn = wn * 32 + nb * 8 + (lane >> 2);
                b[nb][0] = Bs[(kk + (lane & 3)) * BSTR + cn];
                b[nb][1] = Bs[(kk + 4 + (lane & 3)) * BSTR + cn];
            }
            #pragma unroll
            for (int ma = 0; ma < 4; ++ma)
                #pragma unroll
                for (int nb = 0; nb < 4; ++nb)
                    mma_tf32(acc[ma][nb], a[ma], b[nb]);
        }
        // single barrier per tile (2 buffers): sync at t covers compute t-1
    }

    #pragma unroll
    for (int ma = 0; ma < 4; ++ma) {
        #pragma unroll
        for (int nb = 0; nb < 4; ++nb) {
            int r  = m0 + wm * 64 + ma * 16 + (lane >> 2);
            int cc = n0 + wn * 32 + nb * 8 + (lane & 3) * 2;
            *(float2*)&Out[(size_t)r * N + cc] =
                make_float2(acc[ma][nb][0], acc[ma][nb][1]);
            *(float2*)&Out[(size_t)(r + 8) * N + cc] =
                make_float2(acc[ma][nb][2], acc[ma][nb][3]);
        }
    }
}

// ---------------------------------------------------------------------------
// Window attention on TF32 mma.sync. Block = one (window, head), 128 threads.
// ---------------------------------------------------------------------------
#define QSTR 52
#define VSTR 56
#define SSTR 68

__global__ __launch_bounds__(128) void win_attn()
{
    extern __shared__ float smw[];
    float* Qs = smw;                    // 64*52 = 3328
    float* Ks = smw + 3328;             // 64*52
    float* Vs = smw + 6656;             // 64*56 = 3584
    float* Ss = smw + 10240;            // 64*68 = 4352

    const int tid  = threadIdx.x;
    const int lane = tid & 31;
    const int wid  = tid >> 5;
    const int head = blockIdx.y;
    const int b    = blockIdx.z;
    const int wy   = blockIdx.x >> 5;
    const int wx   = blockIdx.x & 31;

    const size_t base = ((size_t)b * C3 + (size_t)head * 48) * HW
                      + (size_t)(wy * 8) * WIMG + wx * 8;
    const float* qg = g_qkv + base;
    const float* kg = qg + (size_t)C * HW;
    const float* vg = qg + (size_t)2 * C * HW;
    const float scale = 0.14433756729740643f;   // 48^-0.5

    #pragma unroll
    for (int it = 0; it < 24; ++it) {
        int idx = tid + it * 128;
        int d = idx >> 6, t = idx & 63;
        size_t off = (size_t)d * HW + (size_t)(t >> 3) * WIMG + (t & 7);
        Qs[t * QSTR + d] = to_tf32(qg[off] * scale);
        Ks[t * QSTR + d] = to_tf32(kg[off]);
        Vs[t * VSTR + d] = to_tf32(vg[off]);
    }
    __syncthreads();

    const int r  = lane >> 2;
    const int cq = lane & 3;
    const int row0 = wid * 16 + r;

    float sacc[8][4];
    #pragma unroll
    for (int nb = 0; nb < 8; ++nb)
        #pragma unroll
        for (int v = 0; v < 4; ++v) sacc[nb][v] = 0.f;

    #pragma unroll
    for (int k8 = 0; k8 < 6; ++k8) {
        const int kk = k8 * 8;
        float a[4];
        a[0] = Qs[row0 * QSTR + kk + cq];
        a[1] = Qs[(row0 + 8) * QSTR + kk + cq];
        a[2] = Qs[row0 * QSTR + kk + cq + 4];
        a[3] = Qs[(row0 + 8) * QSTR + kk + cq + 4];
        #pragma unroll
        for (int nb = 0; nb < 8; ++nb) {
            const int cn = nb * 8 + r;
            float bb[2];
            bb[0] = Ks[cn * QSTR + kk + cq];
            bb[1] = Ks[cn * QSTR + kk + 4 + cq];
            mma_tf32(sacc[nb], a, bb);
        }
    }

    float mx0 = -1e30f, mx8 = -1e30f;
    #pragma unroll
    for (int nb = 0; nb < 8; ++nb) {
        mx0 = fmaxf(mx0, fmaxf(sacc[nb][0], sacc[nb][1]));
        mx8 = fmaxf(mx8, fmaxf(sacc[nb][2], sacc[nb][3]));
    }
    mx0 = fmaxf(mx0, __shfl_xor_sync(0xffffffffu, mx0, 1));
    mx0 = fmaxf(mx0, __shfl_xor_sync(0xffffffffu, mx0, 2));
    mx8 = fmaxf(mx8, __shfl_xor_sync(0xffffffffu, mx8, 1));
    mx8 = fmaxf(mx8, __shfl_xor_sync(0xffffffffu, mx8, 2));

    float s0 = 0.f, s8 = 0.f;
    #pragma unroll
    for (int nb = 0; nb < 8; ++nb) {
        sacc[nb][0] = __expf(sacc[nb][0] - mx0); s0 += sacc[nb][0];
        sacc[nb][1] = __expf(sacc[nb][1] - mx0); s0 += sacc[nb][1];
        sacc[nb][2] = __expf(sacc[nb][2] - mx8); s8 += sacc[nb][2];
        sacc[nb][3] = __expf(sacc[nb][3] - mx8); s8 += sacc[nb][3];
    }
    s0 += __shfl_xor_sync(0xffffffffu, s0, 1);
    s0 += __shfl_xor_sync(0xffffffffu, s0, 2);
    s8 += __shfl_xor_sync(0xffffffffu, s8, 1);
    s8 += __shfl_xor_sync(0xffffffffu, s8, 2);
    const float i0 = 1.f / s0, i8 = 1.f / s8;

    #pragma unroll
    for (int nb = 0; nb < 8; ++nb) {
        const int cb = nb * 8 + 2 * cq;
        Ss[row0 * SSTR + cb]           = to_tf32(sacc[nb][0] * i0);
        Ss[row0 * SSTR + cb + 1]       = to_tf32(sacc[nb][1] * i0);
        Ss[(row0 + 8) * SSTR + cb]     = to_tf32(sacc[nb][2] * i8);
        Ss[(row0 + 8) * SSTR + cb + 1] = to_tf32(sacc[nb][3] * i8);
    }
    __syncwarp();

    float oacc[6][4];
    #pragma unroll
    for (int nb = 0; nb < 6; ++nb)
        #pragma unroll
        for (int v = 0; v < 4; ++v) oacc[nb][v] = 0.f;

    #pragma unroll
    for (int k8 = 0; k8 < 8; ++k8) {
        const int kk = k8 * 8;
        float a[4];
        a[0] = Ss[row0 * SSTR + kk + cq];
        a[1] = Ss[(row0 + 8) * SSTR + kk + cq];
        a[2] = Ss[row0 * SSTR + kk + cq + 4];
        a[3] = Ss[(row0 + 8) * SSTR + kk + cq + 4];
        #pragma unroll
        for (int nb = 0; nb < 6; ++nb) {
            const int cn = nb * 8 + r;
            float bb[2];
            bb[0] = Vs[(kk + cq) * VSTR + cn];
            bb[1] = Vs[(kk + 4 + cq) * VSTR + cn];
            mma_tf32(oacc[nb], a, bb);
        }
    }

    float* og = g_attn + ((size_t)b * C + (size_t)head * 48) * HW
              + (size_t)(wy * 8) * WIMG + wx * 8;
    const int t0 = row0, t8 = row0 + 8;
    const size_t p0 = (size_t)(t0 >> 3) * WIMG + (t0 & 7);
    const size_t p8 = (size_t)(t8 >> 3) * WIMG + (t8 & 7);
    #pragma unroll
    for (int nb = 0; nb < 6; ++nb) {
        const int d0 = nb * 8 + 2 * cq;
        og[(size_t)d0 * HW + p0]       = oacc[nb][0];
        og[(size_t)(d0 + 1) * HW + p0] = oacc[nb][1];
        og[(size_t)d0 * HW + p8]       = oacc[nb][2];
        og[(size_t)(d0 + 1) * HW + p8] = oacc[nb][3];
    }
}

// ---------------------------------------------------------------------------
extern "C" void kernel_launch(void* const* d_in, const int* in_sizes, int n_in,
                              void* d_out, int out_size)
{
    const float* x     = (const float*)d_in[0];
    const float* wqkv  = (const float*)d_in[1];
    const float* wproj = (const float*)d_in[2];
    float* out = (float*)d_out;

    float *qkv, *attn;
    cudaGetSymbolAddress((void**)&qkv, g_qkv);
    cudaGetSymbolAddress((void**)&attn, g_attn);

    const int smem_bytes = 2 * BUFBYTES;       // 54272
    const int attn_smem  = 14592 * 4;          // 58368
    cudaFuncSetAttribute(gemm_tf32, cudaFuncAttributeMaxDynamicSharedMemorySize, smem_bytes);
    cudaFuncSetAttribute(win_attn, cudaFuncAttributeMaxDynamicSharedMemorySize, attn_smem);

    // 1) QKV projection: m fast-varying for L2 reuse of X
    dim3 g1(C3 / 128, HW / 256, NB);
    gemm_tf32<<<g1, 512, smem_bytes>>>(wqkv, x, qkv, C3, C, HW);

    // 2) Window attention
    dim3 g2(1024, 8, NB);
    win_attn<<<g2, 128, attn_smem>>>();

    // 3) Output projection
    dim3 g3(C / 128, HW / 256, NB);
    gemm_tf32<<<g3, 512, smem_bytes>>>(wproj, attn, out, C, C, HW);
}

// round 11
// speedup vs baseline: 3.9005x; 1.3718x over previous
#include <cuda_runtime.h>
#include <cuda_fp16.h>
#include <cstdint>
#include <math.h>

#define HW   65536
#define WIMG 256
#define C    384
#define C3   1152
#define NB   2

// Scratch (static device globals — allocation-free kernel_launch)
__device__ float g_qkv[(size_t)NB * C3 * HW];   // [b][3C][h*w]
__device__ float g_attn[(size_t)NB * C * HW];   // [b][C][h*w]

// ---------------------------------------------------------------------------
// helpers
// ---------------------------------------------------------------------------
__device__ __forceinline__ float to_tf32(float x) {
    float r;
    asm("cvt.rna.tf32.f32 %0, %1;" : "=f"(r) : "f"(x));
    return r;
}

__device__ __forceinline__ void mma_tf32(float c[4], const float a[4], const float b[2]) {
    asm volatile(
        "mma.sync.aligned.m16n8k8.row.col.f32.tf32.tf32.f32 "
        "{%0,%1,%2,%3}, {%4,%5,%6,%7}, {%8,%9}, {%0,%1,%2,%3};"
        : "+f"(c[0]), "+f"(c[1]), "+f"(c[2]), "+f"(c[3])
        : "r"(__float_as_uint(a[0])), "r"(__float_as_uint(a[1])),
          "r"(__float_as_uint(a[2])), "r"(__float_as_uint(a[3])),
          "r"(__float_as_uint(b[0])), "r"(__float_as_uint(b[1])));
}

__device__ __forceinline__ void mma_f16(float c[4], const uint32_t a[4], const uint32_t b[2]) {
    asm volatile(
        "mma.sync.aligned.m16n8k16.row.col.f32.f16.f16.f32 "
        "{%0,%1,%2,%3}, {%4,%5,%6,%7}, {%8,%9}, {%0,%1,%2,%3};"
        : "+f"(c[0]), "+f"(c[1]), "+f"(c[2]), "+f"(c[3])
        : "r"(a[0]), "r"(a[1]), "r"(a[2]), "r"(a[3]),
          "r"(b[0]), "r"(b[1]));
}

__device__ __forceinline__ uint32_t pack_h2(float lo, float hi) {
    __half2 h = __floats2half2_rn(lo, hi);
    return *reinterpret_cast<uint32_t*>(&h);
}

// ---------------------------------------------------------------------------
// FP16 tensor-core GEMM: Out[b][m][n] = sum_k W[m][k] * X[b][k][n]
// BM=128, BN=256, BK=32 (fp16). 512 threads = 16 warps (2m x 8n), warp 64x32.
// A smem: uint32 pairs [m][kp], stride 20. B smem: pairs [kp][n], stride 264.
// Grid: blockIdx.x = m (fast) for L2 reuse of X. One barrier per k-tile.
// ---------------------------------------------------------------------------
#define ASTRP 20
#define BSTRP 264
#define A32   (128 * ASTRP)            // 2560 uint32
#define B32   (16 * BSTRP)             // 4224 uint32
#define BUF32 (A32 + B32)              // 6784 uint32 = 27136 B

__global__ __launch_bounds__(512, 1) void gemm_f16(
    const float* __restrict__ Wt, const float* __restrict__ X,
    float* __restrict__ Out, int M, int K, int N)
{
    extern __shared__ uint32_t sm32[];

    const int tid  = threadIdx.x;
    const int lane = tid & 31;
    const int wid  = tid >> 5;
    const int wm   = wid >> 3;       // 0..1
    const int wn   = wid & 7;        // 0..7
    const int m0   = blockIdx.x * 128;
    const int n0   = blockIdx.y * 256;
    X   += (size_t)blockIdx.z * K * N;
    Out += (size_t)blockIdx.z * M * N;

    float acc[4][4][4];
    #pragma unroll
    for (int i = 0; i < 4; i++)
        #pragma unroll
        for (int j = 0; j < 4; j++)
            #pragma unroll
            for (int v = 0; v < 4; v++) acc[i][j][v] = 0.f;

    // A staging: unit q in [0,1024): row=q>>3 (0..127), quad=q&7 (8 quads of 4 floats per 32-k row)
    const int ar0 = tid >> 3, aq0 = tid & 7;              // q = tid
    const int ar1 = (tid + 512) >> 3, aq1 = aq0;          // q = tid+512
    // B staging: unit u in [0,1024): kp=u>>6 (0..15), nq=u&63
    const int bkp0 = tid >> 6, bnq = tid & 63;            // u = tid
    const int bkp1 = bkp0 + 8;                            // u = tid+512

    float4 ra0, ra1, rb0a, rb0b, rb1a, rb1b;

    // prologue (kt = 0)
    ra0  = *(const float4*)&Wt[(size_t)(m0 + ar0) * K + aq0 * 4];
    ra1  = *(const float4*)&Wt[(size_t)(m0 + ar1) * K + aq1 * 4];
    rb0a = *(const float4*)&X[(size_t)(2 * bkp0) * N + n0 + bnq * 4];
    rb0b = *(const float4*)&X[(size_t)(2 * bkp0 + 1) * N + n0 + bnq * 4];
    rb1a = *(const float4*)&X[(size_t)(2 * bkp1) * N + n0 + bnq * 4];
    rb1b = *(const float4*)&X[(size_t)(2 * bkp1 + 1) * N + n0 + bnq * 4];

    const int ntile = K / 32;
    for (int t = 0; t < ntile; ++t) {
        uint32_t* As = sm32 + (t & 1) * BUF32;
        uint32_t* Bs = As + A32;

        // store A pairs (row-major k): quad*4 floats -> 2 uint32 at [row*20 + quad*2]
        {
            uint2 p0 = make_uint2(pack_h2(ra0.x, ra0.y), pack_h2(ra0.z, ra0.w));
            uint2 p1 = make_uint2(pack_h2(ra1.x, ra1.y), pack_h2(ra1.z, ra1.w));
            *(uint2*)&As[ar0 * ASTRP + aq0 * 2] = p0;
            *(uint2*)&As[ar1 * ASTRP + aq1 * 2] = p1;
            // store B pairs: (k,n),(k+1,n) packed; uint4 at [kp*264 + nq*4]
            uint4 q0 = make_uint4(pack_h2(rb0a.x, rb0b.x), pack_h2(rb0a.y, rb0b.y),
                                  pack_h2(rb0a.z, rb0b.z), pack_h2(rb0a.w, rb0b.w));
            uint4 q1 = make_uint4(pack_h2(rb1a.x, rb1b.x), pack_h2(rb1a.y, rb1b.y),
                                  pack_h2(rb1a.z, rb1b.z), pack_h2(rb1a.w, rb1b.w));
            *(uint4*)&Bs[bkp0 * BSTRP + bnq * 4] = q0;
            *(uint4*)&Bs[bkp1 * BSTRP + bnq * 4] = q1;
        }
        __syncthreads();

        // prefetch next tile
        if (t + 1 < ntile) {
            const int kt = (t + 1) * 32;
            ra0  = *(const float4*)&Wt[(size_t)(m0 + ar0) * K + kt + aq0 * 4];
            ra1  = *(const float4*)&Wt[(size_t)(m0 + ar1) * K + kt + aq1 * 4];
            rb0a = *(const float4*)&X[(size_t)(kt + 2 * bkp0) * N + n0 + bnq * 4];
            rb0b = *(const float4*)&X[(size_t)(kt + 2 * bkp0 + 1) * N + n0 + bnq * 4];
            rb1a = *(const float4*)&X[(size_t)(kt + 2 * bkp1) * N + n0 + bnq * 4];
            rb1b = *(const float4*)&X[(size_t)(kt + 2 * bkp1 + 1) * N + n0 + bnq * 4];
        }

        // compute: 2 k16 steps
        #pragma unroll
        for (int ks = 0; ks < 2; ++ks) {
            const int cc = ks * 8 + (lane & 3);     // pair column
            uint32_t a[4][4], b[4][2];
            #pragma unroll
            for (int ma = 0; ma < 4; ++ma) {
                int r0 = wm * 64 + ma * 16 + (lane >> 2);
                a[ma][0] = As[r0 * ASTRP + cc];
                a[ma][1] = As[(r0 + 8) * ASTRP + cc];
                a[ma][2] = As[r0 * ASTRP + cc + 4];
                a[ma][3] = As[(r0 + 8) * ASTRP + cc + 4];
            }
            #pragma unroll
            for (int nb = 0; nb < 4; ++nb) {
                int cn = wn * 32 + nb * 8 + (lane >> 2);
                b[nb][0] = Bs[(ks * 8 + (lane & 3)) * BSTRP + cn];
                b[nb][1] = Bs[(ks * 8 + 4 + (lane & 3)) * BSTRP + cn];
            }
            #pragma unroll
            for (int ma = 0; ma < 4; ++ma)
                #pragma unroll
                for (int nb = 0; nb < 4; ++nb)
                    mma_f16(acc[ma][nb], a[ma], b[nb]);
        }
        // single barrier per tile (2 buffers)
    }

    #pragma unroll
    for (int ma = 0; ma < 4; ++ma) {
        #pragma unroll
        for (int nb = 0; nb < 4; ++nb) {
            int r  = m0 + wm * 64 + ma * 16 + (lane >> 2);
            int cc = n0 + wn * 32 + nb * 8 + (lane & 3) * 2;
            *(float2*)&Out[(size_t)r * N + cc] =
                make_float2(acc[ma][nb][0], acc[ma][nb][1]);
            *(float2*)&Out[(size_t)(r + 8) * N + cc] =
                make_float2(acc[ma][nb][2], acc[ma][nb][3]);
        }
    }
}

// ---------------------------------------------------------------------------
// Window attention on TF32 mma.sync. Block = one (window, head), 128 threads.
// (unchanged from R8)
// ---------------------------------------------------------------------------
#define QSTR 52
#define VSTR 56
#define SSTR 68

__global__ __launch_bounds__(128) void win_attn()
{
    extern __shared__ float smw[];
    float* Qs = smw;                    // 64*52 = 3328
    float* Ks = smw + 3328;             // 64*52
    float* Vs = smw + 6656;             // 64*56 = 3584
    float* Ss = smw + 10240;            // 64*68 = 4352

    const int tid  = threadIdx.x;
    const int lane = tid & 31;
    const int wid  = tid >> 5;
    const int head = blockIdx.y;
    const int b    = blockIdx.z;
    const int wy   = blockIdx.x >> 5;
    const int wx   = blockIdx.x & 31;

    const size_t base = ((size_t)b * C3 + (size_t)head * 48) * HW
                      + (size_t)(wy * 8) * WIMG + wx * 8;
    const float* qg = g_qkv + base;
    const float* kg = qg + (size_t)C * HW;
    const float* vg = qg + (size_t)2 * C * HW;
    const float scale = 0.14433756729740643f;   // 48^-0.5

    #pragma unroll
    for (int it = 0; it < 24; ++it) {
        int idx = tid + it * 128;
        int d = idx >> 6, t = idx & 63;
        size_t off = (size_t)d * HW + (size_t)(t >> 3) * WIMG + (t & 7);
        Qs[t * QSTR + d] = to_tf32(qg[off] * scale);
        Ks[t * QSTR + d] = to_tf32(kg[off]);
        Vs[t * VSTR + d] = to_tf32(vg[off]);
    }
    __syncthreads();

    const int r  = lane >> 2;
    const int cq = lane & 3;
    const int row0 = wid * 16 + r;

    float sacc[8][4];
    #pragma unroll
    for (int nb = 0; nb < 8; ++nb)
        #pragma unroll
        for (int v = 0; v < 4; ++v) sacc[nb][v] = 0.f;

    #pragma unroll
    for (int k8 = 0; k8 < 6; ++k8) {
        const int kk = k8 * 8;
        float a[4];
        a[0] = Qs[row0 * QSTR + kk + cq];
        a[1] = Qs[(row0 + 8) * QSTR + kk + cq];
        a[2] = Qs[row0 * QSTR + kk + cq + 4];
        a[3] = Qs[(row0 + 8) * QSTR + kk + cq + 4];
        #pragma unroll
        for (int nb = 0; nb < 8; ++nb) {
            const int cn = nb * 8 + r;
            float bb[2];
            bb[0] = Ks[cn * QSTR + kk + cq];
            bb[1] = Ks[cn * QSTR + kk + 4 + cq];
            mma_tf32(sacc[nb], a, bb);
        }
    }

    float mx0 = -1e30f, mx8 = -1e30f;
    #pragma unroll
    for (int nb = 0; nb < 8; ++nb) {
        mx0 = fmaxf(mx0, fmaxf(sacc[nb][0], sacc[nb][1]));
        mx8 = fmaxf(mx8, fmaxf(sacc[nb][2], sacc[nb][3]));
    }
    mx0 = fmaxf(mx0, __shfl_xor_sync(0xffffffffu, mx0, 1));
    mx0 = fmaxf(mx0, __shfl_xor_sync(0xffffffffu, mx0, 2));
    mx8 = fmaxf(mx8, __shfl_xor_sync(0xffffffffu, mx8, 1));
    mx8 = fmaxf(mx8, __shfl_xor_sync(0xffffffffu, mx8, 2));

    float s0 = 0.f, s8 = 0.f;
    #pragma unroll
    for (int nb = 0; nb < 8; ++nb) {
        sacc[nb][0] = __expf(sacc[nb][0] - mx0); s0 += sacc[nb][0];
        sacc[nb][1] = __expf(sacc[nb][1] - mx0); s0 += sacc[nb][1];
        sacc[nb][2] = __expf(sacc[nb][2] - mx8); s8 += sacc[nb][2];
        sacc[nb][3] = __expf(sacc[nb][3] - mx8); s8 += sacc[nb][3];
    }
    s0 += __shfl_xor_sync(0xffffffffu, s0, 1);
    s0 += __shfl_xor_sync(0xffffffffu, s0, 2);
    s8 += __shfl_xor_sync(0xffffffffu, s8, 1);
    s8 += __shfl_xor_sync(0xffffffffu, s8, 2);
    const float i0 = 1.f / s0, i8 = 1.f / s8;

    #pragma unroll
    for (int nb = 0; nb < 8; ++nb) {
        const int cb = nb * 8 + 2 * cq;
        Ss[row0 * SSTR + cb]           = to_tf32(sacc[nb][0] * i0);
        Ss[row0 * SSTR + cb + 1]       = to_tf32(sacc[nb][1] * i0);
        Ss[(row0 + 8) * SSTR + cb]     = to_tf32(sacc[nb][2] * i8);
        Ss[(row0 + 8) * SSTR + cb + 1] = to_tf32(sacc[nb][3] * i8);
    }
    __syncwarp();

    float oacc[6][4];
    #pragma unroll
    for (int nb = 0; nb < 6; ++nb)
        #pragma unroll
        for (int v = 0; v < 4; ++v) oacc[nb][v] = 0.f;

    #pragma unroll
    for (int k8 = 0; k8 < 8; ++k8) {
        const int kk = k8 * 8;
        float a[4];
        a[0] = Ss[row0 * SSTR + kk + cq];
        a[1] = Ss[(row0 + 8) * SSTR + kk + cq];
        a[2] = Ss[row0 * SSTR + kk + cq + 4];
        a[3] = Ss[(row0 + 8) * SSTR + kk + cq + 4];
        #pragma unroll
        for (int nb = 0; nb < 6; ++nb) {
            const int cn = nb * 8 + r;
            float bb[2];
            bb[0] = Vs[(kk + cq) * VSTR + cn];
            bb[1] = Vs[(kk + 4 + cq) * VSTR + cn];
            mma_tf32(oacc[nb], a, bb);
        }
    }

    float* og = g_attn + ((size_t)b * C + (size_t)head * 48) * HW
              + (size_t)(wy * 8) * WIMG + wx * 8;
    const int t0 = row0, t8 = row0 + 8;
    const size_t p0 = (size_t)(t0 >> 3) * WIMG + (t0 & 7);
    const size_t p8 = (size_t)(t8 >> 3) * WIMG + (t8 & 7);
    #pragma unroll
    for (int nb = 0; nb < 6; ++nb) {
        const int d0 = nb * 8 + 2 * cq;
        og[(size_t)d0 * HW + p0]       = oacc[nb][0];
        og[(size_t)(d0 + 1) * HW + p0] = oacc[nb][1];
        og[(size_t)d0 * HW + p8]       = oacc[nb][2];
        og[(size_t)(d0 + 1) * HW + p8] = oacc[nb][3];
    }
}

// ---------------------------------------------------------------------------
extern "C" void kernel_launch(void* const* d_in, const int* in_sizes, int n_in,
                              void* d_out, int out_size)
{
    const float* x     = (const float*)d_in[0];
    const float* wqkv  = (const float*)d_in[1];
    const float* wproj = (const float*)d_in[2];
    float* out = (float*)d_out;

    float *qkv, *attn;
    cudaGetSymbolAddress((void**)&qkv, g_qkv);
    cudaGetSymbolAddress((void**)&attn, g_attn);

    const int smem_bytes = 2 * BUF32 * 4;      // 54272
    const int attn_smem  = 14592 * 4;          // 58368
    cudaFuncSetAttribute(gemm_f16, cudaFuncAttributeMaxDynamicSharedMemorySize, smem_bytes);
    cudaFuncSetAttribute(win_attn, cudaFuncAttributeMaxDynamicSharedMemorySize, attn_smem);

    // 1) QKV projection: m fast-varying for L2 reuse of X
    dim3 g1(C3 / 128, HW / 256, NB);
    gemm_f16<<<g1, 512, smem_bytes>>>(wqkv, x, qkv, C3, C, HW);

    // 2) Window attention
    dim3 g2(1024, 8, NB);
    win_attn<<<g2, 128, attn_smem>>>();

    // 3) Output projection
    dim3 g3(C / 128, HW / 256, NB);
    gemm_f16<<<g3, 512, smem_bytes>>>(wproj, attn, out, C, C, HW);
}

// round 13
// speedup vs baseline: 4.4092x; 1.1304x over previous
#include <cuda_runtime.h>
#include <cuda_fp16.h>
#include <cstdint>
#include <math.h>

#define HW   65536
#define WIMG 256
#define C    384
#define C3   1152
#define NB   2

// Scratch (static device globals — allocation-free kernel_launch)
__device__ __half g_xh[(size_t)NB * C * HW];     // x in fp16
__device__ __half g_wqkvh[(size_t)C3 * C];
__device__ __half g_wprojh[(size_t)C * C];
__device__ __half g_qkvh[(size_t)NB * C3 * HW];  // [b][3C][h*w] fp16
__device__ __half g_attnh[(size_t)NB * C * HW];  // [b][C][h*w] fp16

// ---------------------------------------------------------------------------
// helpers
// ---------------------------------------------------------------------------
__device__ __forceinline__ void mma_f16(float c[4], const uint32_t a[4], const uint32_t b[2]) {
    asm volatile(
        "mma.sync.aligned.m16n8k16.row.col.f32.f16.f16.f32 "
        "{%0,%1,%2,%3}, {%4,%5,%6,%7}, {%8,%9}, {%0,%1,%2,%3};"
        : "+f"(c[0]), "+f"(c[1]), "+f"(c[2]), "+f"(c[3])
        : "r"(a[0]), "r"(a[1]), "r"(a[2]), "r"(a[3]),
          "r"(b[0]), "r"(b[1]));
}

__device__ __forceinline__ uint32_t pack_h2(float lo, float hi) {
    __half2 h = __floats2half2_rn(lo, hi);
    return *reinterpret_cast<uint32_t*>(&h);
}
__device__ __forceinline__ uint32_t pack2h(__half lo, __half hi) {
    __half2 h = __halves2half2(lo, hi);
    return *reinterpret_cast<uint32_t*>(&h);
}
__device__ __forceinline__ uint32_t prmt(uint32_t a, uint32_t b, uint32_t sel) {
    uint32_t r;
    asm("prmt.b32 %0, %1, %2, %3;" : "=r"(r) : "r"(a), "r"(b), "r"(sel));
    return r;
}

// ---------------------------------------------------------------------------
// fp32 -> fp16 convert (n multiple of 4)
// ---------------------------------------------------------------------------
__global__ void cvt_f2h(const float* __restrict__ src, __half* __restrict__ dst, int n4)
{
    int i = blockIdx.x * blockDim.x + threadIdx.x;
    for (; i < n4; i += gridDim.x * blockDim.x) {
        float4 v = *(const float4*)(src + (size_t)i * 4);
        uint2 p = make_uint2(pack_h2(v.x, v.y), pack_h2(v.z, v.w));
        *(uint2*)(dst + (size_t)i * 4) = p;
    }
}

// ---------------------------------------------------------------------------
// FP16 tensor-core GEMM (fp16 in): Out[b][m][n] = sum_k W[m][k]*X[b][k][n]
// BM=128, BN=256, BK=32. 512 threads = 16 warps (2m x 8n), warp 64x32.
// A smem pairs [m][kp] stride 20; B smem pairs [kp][n] stride 264.
// Grid: blockIdx.x = m (fast) for L2 reuse of X. One barrier per k-tile.
// ---------------------------------------------------------------------------
#define ASTRP 20
#define BSTRP 264
#define A32   (128 * ASTRP)
#define B32   (16 * BSTRP)
#define BUF32 (A32 + B32)              // 6784 words = 27136 B

template<bool HALF_OUT>
__global__ __launch_bounds__(512, 1) void gemm_f16(
    const __half* __restrict__ Wt, const __half* __restrict__ X,
    void* __restrict__ OutV, int M, int K, int N)
{
    extern __shared__ uint32_t sm32[];

    const int tid  = threadIdx.x;
    const int lane = tid & 31;
    const int wid  = tid >> 5;
    const int wm   = wid >> 3;
    const int wn   = wid & 7;
    const int m0   = blockIdx.x * 128;
    const int n0   = blockIdx.y * 256;
    X += (size_t)blockIdx.z * K * N;

    float acc[4][4][4];
    #pragma unroll
    for (int i = 0; i < 4; i++)
        #pragma unroll
        for (int j = 0; j < 4; j++)
            #pragma unroll
            for (int v = 0; v < 4; v++) acc[i][j][v] = 0.f;

    // A staging: unit q: row=q>>3 (0..127), quad=q&7 (4 halves each)
    const int ar0 = tid >> 3, aq0 = tid & 7;
    const int ar1 = (tid + 512) >> 3;
    // B staging: kp row = tid>>6 (+8), 4 n per thread
    const int bkp0 = tid >> 6, bnq = tid & 63;
    const int bkp1 = bkp0 + 8;

    uint2 ra0, ra1, rb0a, rb0b, rb1a, rb1b;

    ra0  = *(const uint2*)&Wt[(size_t)(m0 + ar0) * K + aq0 * 4];
    ra1  = *(const uint2*)&Wt[(size_t)(m0 + ar1) * K + aq0 * 4];
    rb0a = *(const uint2*)&X[(size_t)(2 * bkp0) * N + n0 + bnq * 4];
    rb0b = *(const uint2*)&X[(size_t)(2 * bkp0 + 1) * N + n0 + bnq * 4];
    rb1a = *(const uint2*)&X[(size_t)(2 * bkp1) * N + n0 + bnq * 4];
    rb1b = *(const uint2*)&X[(size_t)(2 * bkp1 + 1) * N + n0 + bnq * 4];

    const int ntile = K / 32;
    for (int t = 0; t < ntile; ++t) {
        uint32_t* As = sm32 + (t & 1) * BUF32;
        uint32_t* Bs = As + A32;

        {
            *(uint2*)&As[ar0 * ASTRP + aq0 * 2] = ra0;
            *(uint2*)&As[ar1 * ASTRP + aq0 * 2] = ra1;
            uint4 q0 = make_uint4(prmt(rb0a.x, rb0b.x, 0x5410), prmt(rb0a.x, rb0b.x, 0x7632),
                                  prmt(rb0a.y, rb0b.y, 0x5410), prmt(rb0a.y, rb0b.y, 0x7632));
            uint4 q1 = make_uint4(prmt(rb1a.x, rb1b.x, 0x5410), prmt(rb1a.x, rb1b.x, 0x7632),
                                  prmt(rb1a.y, rb1b.y, 0x5410), prmt(rb1a.y, rb1b.y, 0x7632));
            *(uint4*)&Bs[bkp0 * BSTRP + bnq * 4] = q0;
            *(uint4*)&Bs[bkp1 * BSTRP + bnq * 4] = q1;
        }
        __syncthreads();

        if (t + 1 < ntile) {
            const int kt = (t + 1) * 32;
            ra0  = *(const uint2*)&Wt[(size_t)(m0 + ar0) * K + kt + aq0 * 4];
            ra1  = *(const uint2*)&Wt[(size_t)(m0 + ar1) * K + kt + aq0 * 4];
            rb0a = *(const uint2*)&X[(size_t)(kt + 2 * bkp0) * N + n0 + bnq * 4];
            rb0b = *(const uint2*)&X[(size_t)(kt + 2 * bkp0 + 1) * N + n0 + bnq * 4];
            rb1a = *(const uint2*)&X[(size_t)(kt + 2 * bkp1) * N + n0 + bnq * 4];
            rb1b = *(const uint2*)&X[(size_t)(kt + 2 * bkp1 + 1) * N + n0 + bnq * 4];
        }

        #pragma unroll
        for (int ks = 0; ks < 2; ++ks) {
            const int cc = ks * 8 + (lane & 3);
            uint32_t a[4][4], b[4][2];
            #pragma unroll
            for (int ma = 0; ma < 4; ++ma) {
                int r0 = wm * 64 + ma * 16 + (lane >> 2);
                a[ma][0] = As[r0 * ASTRP + cc];
                a[ma][1] = As[(r0 + 8) * ASTRP + cc];
                a[ma][2] = As[r0 * ASTRP + cc + 4];
                a[ma][3] = As[(r0 + 8) * ASTRP + cc + 4];
            }
            #pragma unroll
            for (int nb = 0; nb < 4; ++nb) {
                int cn = wn * 32 + nb * 8 + (lane >> 2);
                b[nb][0] = Bs[(ks * 8 + (lane & 3)) * BSTRP + cn];
                b[nb][1] = Bs[(ks * 8 + 4 + (lane & 3)) * BSTRP + cn];
            }
            #pragma unroll
            for (int ma = 0; ma < 4; ++ma)
                #pragma unroll
                for (int nb = 0; nb < 4; ++nb)
                    mma_f16(acc[ma][nb], a[ma], b[nb]);
        }
    }

    #pragma unroll
    for (int ma = 0; ma < 4; ++ma) {
        #pragma unroll
        for (int nb = 0; nb < 4; ++nb) {
            int r  = m0 + wm * 64 + ma * 16 + (lane >> 2);
            int cc = n0 + wn * 32 + nb * 8 + (lane & 3) * 2;
            if (HALF_OUT) {
                __half* Out = (__half*)OutV + (size_t)blockIdx.z * M * N;
                *(uint32_t*)&Out[(size_t)r * N + cc] = pack_h2(acc[ma][nb][0], acc[ma][nb][1]);
                *(uint32_t*)&Out[(size_t)(r + 8) * N + cc] = pack_h2(acc[ma][nb][2], acc[ma][nb][3]);
            } else {
                float* Out = (float*)OutV + (size_t)blockIdx.z * M * N;
                *(float2*)&Out[(size_t)r * N + cc] =
                    make_float2(acc[ma][nb][0], acc[ma][nb][1]);
                *(float2*)&Out[(size_t)(r + 8) * N + cc] =
                    make_float2(acc[ma][nb][2], acc[ma][nb][3]);
            }
        }
    }
}

// ---------------------------------------------------------------------------
// Window attention, all fp16 mma. Block = (window, head), 128 threads.
// Qh/Kh: [t][dpair] stride 28 words; Vh: [d][tpair] stride 36; Sh: [t][kpair] 36.
// Static smem 30464 B -> ~7 blocks/SM.
// ---------------------------------------------------------------------------
__global__ __launch_bounds__(128) void win_attn()
{
    __shared__ uint32_t Qh[64 * 28];
    __shared__ uint32_t Kh[64 * 28];
    __shared__ uint32_t Vh[48 * 36];
    __shared__ uint32_t Sh[64 * 36];

    const int tid  = threadIdx.x;
    const int lane = tid & 31;
    const int wid  = tid >> 5;
    const int head = blockIdx.y;
    const int b    = blockIdx.z;
    const int wy   = blockIdx.x >> 5;
    const int wx   = blockIdx.x & 31;

    const size_t base = ((size_t)b * C3 + (size_t)head * 48) * HW
                      + (size_t)(wy * 8) * WIMG + wx * 8;
    const __half* qg = g_qkvh + base;
    const __half* kg = qg + (size_t)C * HW;
    const __half* vg = qg + (size_t)2 * C * HW;
    const float scale = 0.14433756729740643f;   // 48^-0.5

    // Q,K: [t][dp]  (two strided 2B loads, packed)
    #pragma unroll
    for (int it = 0; it < 12; ++it) {
        int idx = tid + it * 128;        // 1536 = 24dp * 64t
        int t = idx & 63, dp = idx >> 6;
        size_t off = (size_t)(dp * 2) * HW + (size_t)(t >> 3) * WIMG + (t & 7);
        Qh[t * 28 + dp] = pack2h(qg[off], qg[off + HW]);
        Kh[t * 28 + dp] = pack2h(kg[off], kg[off + HW]);
    }
    // V: [d][tp]  (one uint32 load: adjacent tokens within a window row)
    #pragma unroll
    for (int it = 0; it < 12; ++it) {
        int idx = tid + it * 128;        // 1536 = 48d * 32tp
        int tp = idx & 31, d = idx >> 5;
        int t = tp * 2;
        size_t off = (size_t)d * HW + (size_t)(t >> 3) * WIMG + (t & 7);
        Vh[d * 36 + tp] = *(const uint32_t*)(vg + off);
    }
    __syncthreads();

    const int r  = lane >> 2;
    const int cq = lane & 3;
    const int row0 = wid * 16 + r;

    // ---- S = Q K^T : 3 k16 steps x 8 n-tiles ----
    float sacc[8][4];
    #pragma unroll
    for (int nb = 0; nb < 8; ++nb)
        #pragma unroll
        for (int v = 0; v < 4; ++v) sacc[nb][v] = 0.f;

    #pragma unroll
    for (int ks = 0; ks < 3; ++ks) {
        const int kk = ks * 8;
        uint32_t a[4];
        a[0] = Qh[row0 * 28 + kk + cq];
        a[1] = Qh[(row0 + 8) * 28 + kk + cq];
        a[2] = Qh[row0 * 28 + kk + cq + 4];
        a[3] = Qh[(row0 + 8) * 28 + kk + cq + 4];
        #pragma unroll
        for (int nb = 0; nb < 8; ++nb) {
            const int cn = nb * 8 + r;
            uint32_t bb[2];
            bb[0] = Kh[cn * 28 + kk + cq];
            bb[1] = Kh[cn * 28 + kk + cq + 4];
            mma_f16(sacc[nb], a, bb);
        }
    }

    // ---- softmax in registers (scale folded into exp arg) ----
    float mx0 = -1e30f, mx8 = -1e30f;
    #pragma unroll
    for (int nb = 0; nb < 8; ++nb) {
        mx0 = fmaxf(mx0, fmaxf(sacc[nb][0], sacc[nb][1]));
        mx8 = fmaxf(mx8, fmaxf(sacc[nb][2], sacc[nb][3]));
    }
    mx0 = fmaxf(mx0, __shfl_xor_sync(0xffffffffu, mx0, 1));
    mx0 = fmaxf(mx0, __shfl_xor_sync(0xffffffffu, mx0, 2));
    mx8 = fmaxf(mx8, __shfl_xor_sync(0xffffffffu, mx8, 1));
    mx8 = fmaxf(mx8, __shfl_xor_sync(0xffffffffu, mx8, 2));

    float s0 = 0.f, s8 = 0.f;
    #pragma unroll
    for (int nb = 0; nb < 8; ++nb) {
        sacc[nb][0] = __expf((sacc[nb][0] - mx0) * scale); s0 += sacc[nb][0];
        sacc[nb][1] = __expf((sacc[nb][1] - mx0) * scale); s0 += sacc[nb][1];
        sacc[nb][2] = __expf((sacc[nb][2] - mx8) * scale); s8 += sacc[nb][2];
        sacc[nb][3] = __expf((sacc[nb][3] - mx8) * scale); s8 += sacc[nb][3];
    }
    s0 += __shfl_xor_sync(0xffffffffu, s0, 1);
    s0 += __shfl_xor_sync(0xffffffffu, s0, 2);
    s8 += __shfl_xor_sync(0xffffffffu, s8, 1);
    s8 += __shfl_xor_sync(0xffffffffu, s8, 2);
    const float i0 = 1.f / s0, i8 = 1.f / s8;

    // store P as fp16 pairs: (c0,c1) are adjacent columns -> one uint32
    #pragma unroll
    for (int nb = 0; nb < 8; ++nb) {
        Sh[row0 * 36 + nb * 4 + cq]       = pack_h2(sacc[nb][0] * i0, sacc[nb][1] * i0);
        Sh[(row0 + 8) * 36 + nb * 4 + cq] = pack_h2(sacc[nb][2] * i8, sacc[nb][3] * i8);
    }
    __syncwarp();

    // ---- O = P V : 4 k16 steps x 6 n-tiles ----
    float oacc[6][4];
    #pragma unroll
    for (int nb = 0; nb < 6; ++nb)
        #pragma unroll
        for (int v = 0; v < 4; ++v) oacc[nb][v] = 0.f;

    #pragma unroll
    for (int ks = 0; ks < 4; ++ks) {
        const int kk = ks * 8;
        uint32_t a[4];
        a[0] = Sh[row0 * 36 + kk + cq];
        a[1] = Sh[(row0 + 8) * 36 + kk + cq];
        a[2] = Sh[row0 * 36 + kk + cq + 4];
        a[3] = Sh[(row0 + 8) * 36 + kk + cq + 4];
        #pragma unroll
        for (int nb = 0; nb < 6; ++nb) {
            const int cn = nb * 8 + r;
            uint32_t bb[2];
            bb[0] = Vh[cn * 36 + kk + cq];
            bb[1] = Vh[cn * 36 + kk + cq + 4];
            mma_f16(oacc[nb], a, bb);
        }
    }

    // ---- store O (fp16, scattered 2B) ----
    __half* og = g_attnh + ((size_t)b * C + (size_t)head * 48) * HW
               + (size_t)(wy * 8) * WIMG + wx * 8;
    const int t0 = row0, t8 = row0 + 8;
    const size_t p0 = (size_t)(t0 >> 3) * WIMG + (t0 & 7);
    const size_t p8 = (size_t)(t8 >> 3) * WIMG + (t8 & 7);
    #pragma unroll
    for (int nb = 0; nb < 6; ++nb) {
        const int d0 = nb * 8 + 2 * cq;
        og[(size_t)d0 * HW + p0]       = __float2half(oacc[nb][0]);
        og[(size_t)(d0 + 1) * HW + p0] = __float2half(oacc[nb][1]);
        og[(size_t)d0 * HW + p8]       = __float2half(oacc[nb][2]);
        og[(size_t)(d0 + 1) * HW + p8] = __float2half(oacc[nb][3]);
    }
}

// ---------------------------------------------------------------------------
extern "C" void kernel_launch(void* const* d_in, const int* in_sizes, int n_in,
                              void* d_out, int out_size)
{
    const float* x     = (const float*)d_in[0];
    const float* wqkv  = (const float*)d_in[1];
    const float* wproj = (const float*)d_in[2];
    float* out = (float*)d_out;

    __half *xh, *wqkvh, *wprojh, *qkvh, *attnh;
    cudaGetSymbolAddress((void**)&xh,     g_xh);
    cudaGetSymbolAddress((void**)&wqkvh,  g_wqkvh);
    cudaGetSymbolAddress((void**)&wprojh, g_wprojh);
    cudaGetSymbolAddress((void**)&qkvh,   g_qkvh);
    cudaGetSymbolAddress((void**)&attnh,  g_attnh);

    const int smem_bytes = 2 * BUF32 * 4;      // 54272
    cudaFuncSetAttribute(gemm_f16<true>,  cudaFuncAttributeMaxDynamicSharedMemorySize, smem_bytes);
    cudaFuncSetAttribute(gemm_f16<false>, cudaFuncAttributeMaxDynamicSharedMemorySize, smem_bytes);

    // 0) fp32 -> fp16 conversions
    cvt_f2h<<<4096, 256>>>(x, xh, NB * C * HW / 4);
    cvt_f2h<<<256, 256>>>(wqkv, wqkvh, C3 * C / 4);
    cvt_f2h<<<128, 256>>>(wproj, wprojh, C * C / 4);

    // 1) QKV projection (fp16 out): m fast-varying for L2 reuse of X
    dim3 g1(C3 / 128, HW / 256, NB);
    gemm_f16<true><<<g1, 512, smem_bytes>>>(wqkvh, xh, qkvh, C3, C, HW);

    // 2) Window attention (fp16 in/out)
    dim3 g2(1024, 8, NB);
    win_attn<<<g2, 128>>>();

    // 3) Output projection (fp32 out)
    dim3 g3(C / 128, HW / 256, NB);
    gemm_f16<false><<<g3, 512, smem_bytes>>>(wprojh, attnh, out, C, C, HW);
}

// round 14
// speedup vs baseline: 5.0319x; 1.1412x over previous
#include <cuda_runtime.h>
#include <cuda_fp16.h>
#include <cstdint>
#include <math.h>

#define HW   65536
#define WIMG 256
#define C    384
#define C3   1152
#define NB   2

// Scratch (static device globals — allocation-free kernel_launch)
__device__ __half g_xh[(size_t)NB * C * HW];     // x in fp16
__device__ __half g_wqkvh[(size_t)C3 * C];
__device__ __half g_wprojh[(size_t)C * C];
__device__ __half g_qkvh[(size_t)NB * C3 * HW];  // [b][3C][h*w] fp16
__device__ __half g_attnh[(size_t)NB * C * HW];  // [b][C][h*w] fp16

// ---------------------------------------------------------------------------
// helpers
// ---------------------------------------------------------------------------
__device__ __forceinline__ void mma_f16(float c[4], const uint32_t a[4], const uint32_t b[2]) {
    asm volatile(
        "mma.sync.aligned.m16n8k16.row.col.f32.f16.f16.f32 "
        "{%0,%1,%2,%3}, {%4,%5,%6,%7}, {%8,%9}, {%0,%1,%2,%3};"
        : "+f"(c[0]), "+f"(c[1]), "+f"(c[2]), "+f"(c[3])
        : "r"(a[0]), "r"(a[1]), "r"(a[2]), "r"(a[3]),
          "r"(b[0]), "r"(b[1]));
}
__device__ __forceinline__ uint32_t pack_h2(float lo, float hi) {
    __half2 h = __floats2half2_rn(lo, hi);
    return *reinterpret_cast<uint32_t*>(&h);
}
__device__ __forceinline__ uint32_t pack2h(__half lo, __half hi) {
    __half2 h = __halves2half2(lo, hi);
    return *reinterpret_cast<uint32_t*>(&h);
}
__device__ __forceinline__ uint32_t smem_u32(const void* p) {
    uint32_t a;
    asm("{ .reg .u64 t; cvta.to.shared.u64 t, %1; cvt.u32.u64 %0, t; }" : "=r"(a) : "l"(p));
    return a;
}
__device__ __forceinline__ void cp16(uint32_t dst, const void* src) {
    asm volatile("cp.async.cg.shared.global [%0], [%1], 16;" :: "r"(dst), "l"(src));
}
__device__ __forceinline__ void ldsm_x4(uint32_t& r0, uint32_t& r1, uint32_t& r2, uint32_t& r3, uint32_t a) {
    asm volatile("ldmatrix.sync.aligned.m8n8.x4.shared.b16 {%0,%1,%2,%3}, [%4];"
                 : "=r"(r0), "=r"(r1), "=r"(r2), "=r"(r3) : "r"(a));
}
__device__ __forceinline__ void ldsm_x4t(uint32_t& r0, uint32_t& r1, uint32_t& r2, uint32_t& r3, uint32_t a) {
    asm volatile("ldmatrix.sync.aligned.m8n8.x4.trans.shared.b16 {%0,%1,%2,%3}, [%4];"
                 : "=r"(r0), "=r"(r1), "=r"(r2), "=r"(r3) : "r"(a));
}

// ---------------------------------------------------------------------------
// fp32 -> fp16 convert (n multiple of 4)
// ---------------------------------------------------------------------------
__global__ void cvt_f2h(const float* __restrict__ src, __half* __restrict__ dst, int n4)
{
    int i = blockIdx.x * blockDim.x + threadIdx.x;
    for (; i < n4; i += gridDim.x * blockDim.x) {
        float4 v = *(const float4*)(src + (size_t)i * 4);
        uint2 p = make_uint2(pack_h2(v.x, v.y), pack_h2(v.z, v.w));
        *(uint2*)(dst + (size_t)i * 4) = p;
    }
}

// ---------------------------------------------------------------------------
// FP16 GEMM, cp.async 3-stage pipeline + ldmatrix + XOR swizzle.
// Out[b][m][n] = sum_k W[m][k]*X[b][k][n].
// BM=128, BN=256, BK=32. 512 threads = 16 warps (2m x 8n), warp 64x32.
// A smem: row m = 64B (32 halves), chunk c at c^((m>>1)&3). 8KB/stage.
// B smem: row k = 512B (256 halves), chunk cn at cn^(k&7). 16KB/stage.
// ---------------------------------------------------------------------------
#define ASTG 8192
#define BSTG 16384
#define STGB (ASTG + BSTG)     // 24576
#define NSTAGE 3

template<bool HALF_OUT>
__global__ __launch_bounds__(512, 1) void gemm_f16(
    const __half* __restrict__ Wt, const __half* __restrict__ X,
    void* __restrict__ OutV, int M, int K, int N)
{
    extern __shared__ char smc[];
    const uint32_t sb = smem_u32(smc);

    const int tid  = threadIdx.x;
    const int lane = tid & 31;
    const int wid  = tid >> 5;
    const int wm   = wid >> 3;       // 0..1
    const int wn   = wid & 7;        // 0..7
    const int m0   = blockIdx.x * 128;
    const int n0   = blockIdx.y * 256;
    X += (size_t)blockIdx.z * K * N;

    float acc[4][4][4];
    #pragma unroll
    for (int i = 0; i < 4; i++)
        #pragma unroll
        for (int j = 0; j < 4; j++)
            #pragma unroll
            for (int v = 0; v < 4; v++) acc[i][j][v] = 0.f;

    // ---- cp.async source/dest (per thread, stage-base added later) ----
    const int amr = tid >> 2, acc4 = tid & 3;          // A: m row, k-chunk
    const __half* aSrc = Wt + (size_t)(m0 + amr) * K + acc4 * 8;
    const uint32_t aOff = amr * 64 + ((acc4 ^ ((amr >> 1) & 3)) * 16);

    const int bkr = tid >> 4, bcn = tid & 15;          // B: k row, cn chunk (and +16)
    const __half* bSrc = X + (size_t)bkr * N + n0 + bcn * 8;
    const uint32_t bOff0 = ASTG + bkr * 512 + ((bcn ^ (bkr & 7)) * 16);
    const uint32_t bOff1 = bOff0 + 256;                 // cn+16: bit4 untouched by ^(k&7)

    // ---- ldmatrix addresses (per warp/lane, stage-base added later) ----
    // A x4: lane l -> row m = M0 + (l&15), chunk c = ks*2 + (l>>4)
    uint32_t preA[4][2];
    #pragma unroll
    for (int ma = 0; ma < 4; ++ma) {
        int m = wm * 64 + ma * 16 + (lane & 15);
        #pragma unroll
        for (int ks = 0; ks < 2; ++ks) {
            int c = ks * 2 + (lane >> 4);
            preA[ma][ks] = m * 64 + ((c ^ ((m >> 1) & 3)) * 16);
        }
    }
    // B x4.trans: lane l -> row k = ks*16 + (l&15 with bit3 = +8), cn = CN + (l>>4)
    uint32_t preB[2][2];
    #pragma unroll
    for (int nb2 = 0; nb2 < 2; ++nb2) {
        #pragma unroll
        for (int ks = 0; ks < 2; ++ks) {
            int k  = ks * 16 + (lane & 15);
            int cn = wn * 4 + nb2 * 2 + (lane >> 4);
            preB[nb2][ks] = ASTG + k * 512 + ((cn ^ (k & 7)) * 16);
        }
    }

    const int ntile = K / 32;

    // ---- prologue: stages 0,1 ----
    #pragma unroll
    for (int s = 0; s < 2; ++s) {
        const uint32_t base = sb + s * STGB;
        const size_t kt = (size_t)s * 32;
        cp16(base + aOff, aSrc + kt);
        cp16(base + bOff0, bSrc + kt * N);
        cp16(base + bOff1, bSrc + kt * N + 128);
        asm volatile("cp.async.commit_group;");
    }

    for (int t = 0; t < ntile; ++t) {
        asm volatile("cp.async.wait_group 1;");
        __syncthreads();
        const uint32_t base = sb + (t % NSTAGE) * STGB;

        #pragma unroll
        for (int ks = 0; ks < 2; ++ks) {
            uint32_t a[4][4], b[2][4];
            #pragma unroll
            for (int ma = 0; ma < 4; ++ma)
                ldsm_x4(a[ma][0], a[ma][1], a[ma][2], a[ma][3], base + preA[ma][ks]);
            #pragma unroll
            for (int nb2 = 0; nb2 < 2; ++nb2)
                ldsm_x4t(b[nb2][0], b[nb2][1], b[nb2][2], b[nb2][3], base + preB[nb2][ks]);
            #pragma unroll
            for (int ma = 0; ma < 4; ++ma) {
                #pragma unroll
                for (int nb2 = 0; nb2 < 2; ++nb2) {
                    mma_f16(acc[ma][nb2 * 2],     a[ma], &b[nb2][0]);
                    mma_f16(acc[ma][nb2 * 2 + 1], a[ma], &b[nb2][2]);
                }
            }
        }

        if (t + 2 < ntile) {
            const uint32_t nbase = sb + ((t + 2) % NSTAGE) * STGB;
            const size_t kt = (size_t)(t + 2) * 32;
            cp16(nbase + aOff, aSrc + kt);
            cp16(nbase + bOff0, bSrc + kt * N);
            cp16(nbase + bOff1, bSrc + kt * N + 128);
        }
        asm volatile("cp.async.commit_group;");
    }

    #pragma unroll
    for (int ma = 0; ma < 4; ++ma) {
        #pragma unroll
        for (int nb = 0; nb < 4; ++nb) {
            int r  = m0 + wm * 64 + ma * 16 + (lane >> 2);
            int cc = n0 + wn * 32 + nb * 8 + (lane & 3) * 2;
            if (HALF_OUT) {
                __half* Out = (__half*)OutV + (size_t)blockIdx.z * M * N;
                *(uint32_t*)&Out[(size_t)r * N + cc] = pack_h2(acc[ma][nb][0], acc[ma][nb][1]);
                *(uint32_t*)&Out[(size_t)(r + 8) * N + cc] = pack_h2(acc[ma][nb][2], acc[ma][nb][3]);
            } else {
                float* Out = (float*)OutV + (size_t)blockIdx.z * M * N;
                *(float2*)&Out[(size_t)r * N + cc] =
                    make_float2(acc[ma][nb][0], acc[ma][nb][1]);
                *(float2*)&Out[(size_t)(r + 8) * N + cc] =
                    make_float2(acc[ma][nb][2], acc[ma][nb][3]);
            }
        }
    }
}

// ---------------------------------------------------------------------------
// Window attention, all fp16 mma. Block = (window, head), 128 threads.
// (unchanged from R13)
// ---------------------------------------------------------------------------
__global__ __launch_bounds__(128) void win_attn()
{
    __shared__ uint32_t Qh[64 * 28];
    __shared__ uint32_t Kh[64 * 28];
    __shared__ uint32_t Vh[48 * 36];
    __shared__ uint32_t Sh[64 * 36];

    const int tid  = threadIdx.x;
    const int lane = tid & 31;
    const int wid  = tid >> 5;
    const int head = blockIdx.y;
    const int b    = blockIdx.z;
    const int wy   = blockIdx.x >> 5;
    const int wx   = blockIdx.x & 31;

    const size_t base = ((size_t)b * C3 + (size_t)head * 48) * HW
                      + (size_t)(wy * 8) * WIMG + wx * 8;
    const __half* qg = g_qkvh + base;
    const __half* kg = qg + (size_t)C * HW;
    const __half* vg = qg + (size_t)2 * C * HW;
    const float scale = 0.14433756729740643f;   // 48^-0.5

    #pragma unroll
    for (int it = 0; it < 12; ++it) {
        int idx = tid + it * 128;        // 1536 = 24dp * 64t
        int t = idx & 63, dp = idx >> 6;
        size_t off = (size_t)(dp * 2) * HW + (size_t)(t >> 3) * WIMG + (t & 7);
        Qh[t * 28 + dp] = pack2h(qg[off], qg[off + HW]);
        Kh[t * 28 + dp] = pack2h(kg[off], kg[off + HW]);
    }
    #pragma unroll
    for (int it = 0; it < 12; ++it) {
        int idx = tid + it * 128;        // 1536 = 48d * 32tp
        int tp = idx & 31, d = idx >> 5;
        int t = tp * 2;
        size_t off = (size_t)d * HW + (size_t)(t >> 3) * WIMG + (t & 7);
        Vh[d * 36 + tp] = *(const uint32_t*)(vg + off);
    }
    __syncthreads();

    const int r  = lane >> 2;
    const int cq = lane & 3;
    const int row0 = wid * 16 + r;

    float sacc[8][4];
    #pragma unroll
    for (int nb = 0; nb < 8; ++nb)
        #pragma unroll
        for (int v = 0; v < 4; ++v) sacc[nb][v] = 0.f;

    #pragma unroll
    for (int ks = 0; ks < 3; ++ks) {
        const int kk = ks * 8;
        uint32_t a[4];
        a[0] = Qh[row0 * 28 + kk + cq];
        a[1] = Qh[(row0 + 8) * 28 + kk + cq];
        a[2] = Qh[row0 * 28 + kk + cq + 4];
        a[3] = Qh[(row0 + 8) * 28 + kk + cq + 4];
        #pragma unroll
        for (int nb = 0; nb < 8; ++nb) {
            const int cn = nb * 8 + r;
            uint32_t bb[2];
            bb[0] = Kh[cn * 28 + kk + cq];
            bb[1] = Kh[cn * 28 + kk + cq + 4];
            mma_f16(sacc[nb], a, bb);
        }
    }

    float mx0 = -1e30f, mx8 = -1e30f;
    #pragma unroll
    for (int nb = 0; nb < 8; ++nb) {
        mx0 = fmaxf(mx0, fmaxf(sacc[nb][0], sacc[nb][1]));
        mx8 = fmaxf(mx8, fmaxf(sacc[nb][2], sacc[nb][3]));
    }
    mx0 = fmaxf(mx0, __shfl_xor_sync(0xffffffffu, mx0, 1));
    mx0 = fmaxf(mx0, __shfl_xor_sync(0xffffffffu, mx0, 2));
    mx8 = fmaxf(mx8, __shfl_xor_sync(0xffffffffu, mx8, 1));
    mx8 = fmaxf(mx8, __shfl_xor_sync(0xffffffffu, mx8, 2));

    float s0 = 0.f, s8 = 0.f;
    #pragma unroll
    for (int nb = 0; nb < 8; ++nb) {
        sacc[nb][0] = __expf((sacc[nb][0] - mx0) * scale); s0 += sacc[nb][0];
        sacc[nb][1] = __expf((sacc[nb][1] - mx0) * scale); s0 += sacc[nb][1];
        sacc[nb][2] = __expf((sacc[nb][2] - mx8) * scale); s8 += sacc[nb][2];
        sacc[nb][3] = __expf((sacc[nb][3] - mx8) * scale); s8 += sacc[nb][3];
    }
    s0 += __shfl_xor_sync(0xffffffffu, s0, 1);
    s0 += __shfl_xor_sync(0xffffffffu, s0, 2);
    s8 += __shfl_xor_sync(0xffffffffu, s8, 1);
    s8 += __shfl_xor_sync(0xffffffffu, s8, 2);
    const float i0 = 1.f / s0, i8 = 1.f / s8;

    #pragma unroll
    for (int nb = 0; nb < 8; ++nb) {
        Sh[row0 * 36 + nb * 4 + cq]       = pack_h2(sacc[nb][0] * i0, sacc[nb][1] * i0);
        Sh[(row0 + 8) * 36 + nb * 4 + cq] = pack_h2(sacc[nb][2] * i8, sacc[nb][3] * i8);
    }
    __syncwarp();

    float oacc[6][4];
    #pragma unroll
    for (int nb = 0; nb < 6; ++nb)
        #pragma unroll
        for (int v = 0; v < 4; ++v) oacc[nb][v] = 0.f;

    #pragma unroll
    for (int ks = 0; ks < 4; ++ks) {
        const int kk = ks * 8;
        uint32_t a[4];
        a[0] = Sh[row0 * 36 + kk + cq];
        a[1] = Sh[(row0 + 8) * 36 + kk + cq];
        a[2] = Sh[row0 * 36 + kk + cq + 4];
        a[3] = Sh[(row0 + 8) * 36 + kk + cq + 4];
        #pragma unroll
        for (int nb = 0; nb < 6; ++nb) {
            const int cn = nb * 8 + r;
            uint32_t bb[2];
            bb[0] = Vh[cn * 36 + kk + cq];
            bb[1] = Vh[cn * 36 + kk + cq + 4];
            mma_f16(oacc[nb], a, bb);
        }
    }

    __half* og = g_attnh + ((size_t)b * C + (size_t)head * 48) * HW
               + (size_t)(wy * 8) * WIMG + wx * 8;
    const int t0 = row0, t8 = row0 + 8;
    const size_t p0 = (size_t)(t0 >> 3) * WIMG + (t0 & 7);
    const size_t p8 = (size_t)(t8 >> 3) * WIMG + (t8 & 7);
    #pragma unroll
    for (int nb = 0; nb < 6; ++nb) {
        const int d0 = nb * 8 + 2 * cq;
        og[(size_t)d0 * HW + p0]       = __float2half(oacc[nb][0]);
        og[(size_t)(d0 + 1) * HW + p0] = __float2half(oacc[nb][1]);
        og[(size_t)d0 * HW + p8]       = __float2half(oacc[nb][2]);
        og[(size_t)(d0 + 1) * HW + p8] = __float2half(oacc[nb][3]);
    }
}

// ---------------------------------------------------------------------------
extern "C" void kernel_launch(void* const* d_in, const int* in_sizes, int n_in,
                              void* d_out, int out_size)
{
    const float* x     = (const float*)d_in[0];
    const float* wqkv  = (const float*)d_in[1];
    const float* wproj = (const float*)d_in[2];
    float* out = (float*)d_out;

    __half *xh, *wqkvh, *wprojh, *qkvh, *attnh;
    cudaGetSymbolAddress((void**)&xh,     g_xh);
    cudaGetSymbolAddress((void**)&wqkvh,  g_wqkvh);
    cudaGetSymbolAddress((void**)&wprojh, g_wprojh);
    cudaGetSymbolAddress((void**)&qkvh,   g_qkvh);
    cudaGetSymbolAddress((void**)&attnh,  g_attnh);

    const int smem_bytes = NSTAGE * STGB;      // 73728
    cudaFuncSetAttribute(gemm_f16<true>,  cudaFuncAttributeMaxDynamicSharedMemorySize, smem_bytes);
    cudaFuncSetAttribute(gemm_f16<false>, cudaFuncAttributeMaxDynamicSharedMemorySize, smem_bytes);

    // 0) fp32 -> fp16 conversions
    cvt_f2h<<<4096, 256>>>(x, xh, NB * C * HW / 4);
    cvt_f2h<<<256, 256>>>(wqkv, wqkvh, C3 * C / 4);
    cvt_f2h<<<128, 256>>>(wproj, wprojh, C * C / 4);

    // 1) QKV projection (fp16 out): m fast-varying for L2 reuse of X
    dim3 g1(C3 / 128, HW / 256, NB);
    gemm_f16<true><<<g1, 512, smem_bytes>>>(wqkvh, xh, qkvh, C3, C, HW);

    // 2) Window attention (fp16 in/out)
    dim3 g2(1024, 8, NB);
    win_attn<<<g2, 128>>>();

    // 3) Output projection (fp32 out)
    dim3 g3(C / 128, HW / 256, NB);
    gemm_f16<false><<<g3, 512, smem_bytes>>>(wprojh, attnh, out, C, C, HW);
}

// round 17
// speedup vs baseline: 5.2010x; 1.0336x over previous
#include <cuda_runtime.h>
#include <cuda_fp16.h>
#include <cstdint>
#include <math.h>

#define HW   65536
#define WIMG 256
#define C    384
#define C3   1152
#define NB   2

// Scratch. qkv/attn live in WINDOW layout: [b][ch][window][token],
// window = (y>>3)*32 + (x>>3), token = (y&7)*8 + (x&7).
__device__ __half g_xh[(size_t)NB * C * HW];
__device__ __half g_wqkvh[(size_t)C3 * C];
__device__ __half g_wprojh[(size_t)C * C];
__device__ __half g_qkvh[(size_t)NB * C3 * HW];
__device__ __half g_attnh[(size_t)NB * C * HW];

// ---------------------------------------------------------------------------
// helpers
// ---------------------------------------------------------------------------
__device__ __forceinline__ void mma_f16(float c[4], const uint32_t a[4], const uint32_t b[2]) {
    asm volatile(
        "mma.sync.aligned.m16n8k16.row.col.f32.f16.f16.f32 "
        "{%0,%1,%2,%3}, {%4,%5,%6,%7}, {%8,%9}, {%0,%1,%2,%3};"
        : "+f"(c[0]), "+f"(c[1]), "+f"(c[2]), "+f"(c[3])
        : "r"(a[0]), "r"(a[1]), "r"(a[2]), "r"(a[3]),
          "r"(b[0]), "r"(b[1]));
}
__device__ __forceinline__ uint32_t pack_h2(float lo, float hi) {
    __half2 h = __floats2half2_rn(lo, hi);
    return *reinterpret_cast<uint32_t*>(&h);
}
__device__ __forceinline__ uint32_t smem_u32(const void* p) {
    uint32_t a;
    asm("{ .reg .u64 t; cvta.to.shared.u64 t, %1; cvt.u32.u64 %0, t; }" : "=r"(a) : "l"(p));
    return a;
}
__device__ __forceinline__ void cp16(uint32_t dst, const void* src) {
    asm volatile("cp.async.cg.shared.global [%0], [%1], 16;" :: "r"(dst), "l"(src));
}
__device__ __forceinline__ void ldsm_x4(uint32_t& r0, uint32_t& r1, uint32_t& r2, uint32_t& r3, uint32_t a) {
    asm volatile("ldmatrix.sync.aligned.m8n8.x4.shared.b16 {%0,%1,%2,%3}, [%4];"
                 : "=r"(r0), "=r"(r1), "=r"(r2), "=r"(r3) : "r"(a));
}
__device__ __forceinline__ void ldsm_x4t(uint32_t& r0, uint32_t& r1, uint32_t& r2, uint32_t& r3, uint32_t a) {
    asm volatile("ldmatrix.sync.aligned.m8n8.x4.trans.shared.b16 {%0,%1,%2,%3}, [%4];"
                 : "=r"(r0), "=r"(r1), "=r"(r2), "=r"(r3) : "r"(a));
}

// ---------------------------------------------------------------------------
// fp32 -> fp16 convert
// ---------------------------------------------------------------------------
__global__ void cvt_f2h(const float* __restrict__ src, __half* __restrict__ dst, int n4)
{
    int i = blockIdx.x * blockDim.x + threadIdx.x;
    for (; i < n4; i += gridDim.x * blockDim.x) {
        float4 v = *(const float4*)(src + (size_t)i * 4);
        uint2 p = make_uint2(pack_h2(v.x, v.y), pack_h2(v.z, v.w));
        *(uint2*)(dst + (size_t)i * 4) = p;
    }
}

// ---------------------------------------------------------------------------
// FP16 GEMM, cp.async 3-stage + ldmatrix + XOR swizzle (R14 mainloop).
// HALF_OUT: B reads pixel layout, epilogue stores to WINDOW layout (fp16).
// !HALF_OUT: B reads WINDOW layout (dense n), epilogue maps to pixel (fp32).
// ---------------------------------------------------------------------------
#define ASTG 8192
#define BSTG 16384
#define STGB (ASTG + BSTG)
#define NSTAGE 3

template<bool HALF_OUT>
__global__ __launch_bounds__(512, 1) void gemm_f16(
    const __half* __restrict__ Wt, const __half* __restrict__ X,
    void* __restrict__ OutV, int M, int K, int N)
{
    extern __shared__ char smc[];
    const uint32_t sb = smem_u32(smc);

    const int tid  = threadIdx.x;
    const int lane = tid & 31;
    const int wid  = tid >> 5;
    const int wm   = wid >> 3;
    const int wn   = wid & 7;
    const int m0   = blockIdx.x * 128;
    const int n0   = blockIdx.y * 256;
    X += (size_t)blockIdx.z * K * N;

    float acc[4][4][4];
    #pragma unroll
    for (int i = 0; i < 4; i++)
        #pragma unroll
        for (int j = 0; j < 4; j++)
            #pragma unroll
            for (int v = 0; v < 4; v++) acc[i][j][v] = 0.f;

    const int amr = tid >> 2, acc4 = tid & 3;
    const __half* aSrc = Wt + (size_t)(m0 + amr) * K + acc4 * 8;
    const uint32_t aOff = amr * 64 + ((acc4 ^ ((amr >> 1) & 3)) * 16);

    const int bkr = tid >> 4, bcn = tid & 15;
    const __half* bSrc = X + (size_t)bkr * N + n0 + bcn * 8;
    const uint32_t bOff0 = ASTG + bkr * 512 + ((bcn ^ (bkr & 7)) * 16);
    const uint32_t bOff1 = bOff0 + 256;

    uint32_t preA[4][2];
    #pragma unroll
    for (int ma = 0; ma < 4; ++ma) {
        int m = wm * 64 + ma * 16 + (lane & 15);
        #pragma unroll
        for (int ks = 0; ks < 2; ++ks) {
            int c = ks * 2 + (lane >> 4);
            preA[ma][ks] = m * 64 + ((c ^ ((m >> 1) & 3)) * 16);
        }
    }
    uint32_t preB[2][2];
    #pragma unroll
    for (int nb2 = 0; nb2 < 2; ++nb2) {
        #pragma unroll
        for (int ks = 0; ks < 2; ++ks) {
            int k  = ks * 16 + (lane & 15);
            int cn = wn * 4 + nb2 * 2 + (lane >> 4);
            preB[nb2][ks] = ASTG + k * 512 + ((cn ^ (k & 7)) * 16);
        }
    }

    const int ntile = K / 32;

    #pragma unroll
    for (int s = 0; s < 2; ++s) {
        const uint32_t base = sb + s * STGB;
        const size_t kt = (size_t)s * 32;
        cp16(base + aOff, aSrc + kt);
        cp16(base + bOff0, bSrc + kt * N);
        cp16(base + bOff1, bSrc + kt * N + 128);
        asm volatile("cp.async.commit_group;");
    }

    for (int t = 0; t < ntile; ++t) {
        asm volatile("cp.async.wait_group 1;");
        __syncthreads();
        const uint32_t base = sb + (t % NSTAGE) * STGB;

        #pragma unroll
        for (int ks = 0; ks < 2; ++ks) {
            uint32_t a[4][4], b[2][4];
            #pragma unroll
            for (int ma = 0; ma < 4; ++ma)
                ldsm_x4(a[ma][0], a[ma][1], a[ma][2], a[ma][3], base + preA[ma][ks]);
            #pragma unroll
            for (int nb2 = 0; nb2 < 2; ++nb2)
                ldsm_x4t(b[nb2][0], b[nb2][1], b[nb2][2], b[nb2][3], base + preB[nb2][ks]);
            #pragma unroll
            for (int ma = 0; ma < 4; ++ma) {
                #pragma unroll
                for (int nb2 = 0; nb2 < 2; ++nb2) {
                    mma_f16(acc[ma][nb2 * 2],     a[ma], &b[nb2][0]);
                    mma_f16(acc[ma][nb2 * 2 + 1], a[ma], &b[nb2][2]);
                }
            }
        }

        if (t + 2 < ntile) {
            const uint32_t nbase = sb + ((t + 2) % NSTAGE) * STGB;
            const size_t kt = (size_t)(t + 2) * 32;
            cp16(nbase + aOff, aSrc + kt);
            cp16(nbase + bOff0, bSrc + kt * N);
            cp16(nbase + bOff1, bSrc + kt * N + 128);
        }
        asm volatile("cp.async.commit_group;");
    }

    if (HALF_OUT) {
        // pixel n -> window layout. CTA's n-tile = one image row y.
        __half* Out = (__half*)OutV + (size_t)blockIdx.z * M * N;
        const int y  = n0 >> 8;         // N == HW, WIMG == 256
        const int wy = y >> 3, ty = y & 7;
        #pragma unroll
        for (int ma = 0; ma < 4; ++ma) {
            #pragma unroll
            for (int nb = 0; nb < 4; ++nb) {
                int r = m0 + wm * 64 + ma * 16 + (lane >> 2);
                int wofs = (wy * 32 + wn * 4 + nb) * 64 + ty * 8 + (lane & 3) * 2;
                *(uint32_t*)&Out[(size_t)r * N + wofs] = pack_h2(acc[ma][nb][0], acc[ma][nb][1]);
                *(uint32_t*)&Out[(size_t)(r + 8) * N + wofs] = pack_h2(acc[ma][nb][2], acc[ma][nb][3]);
            }
        }
    } else {
        // window-index n -> pixel layout (final fp32 output)
        float* Out = (float*)OutV + (size_t)blockIdx.z * M * N;
        #pragma unroll
        for (int ma = 0; ma < 4; ++ma) {
            #pragma unroll
            for (int nb = 0; nb < 4; ++nb) {
                int r  = m0 + wm * 64 + ma * 16 + (lane >> 2);
                int cc = n0 + wn * 32 + nb * 8 + (lane & 3) * 2;
                int w = cc >> 6, tok = cc & 63;
                int p = ((w >> 5) * 8 + (tok >> 3)) * 256 + (w & 31) * 8 + (tok & 7);
                *(float2*)&Out[(size_t)r * N + p] =
                    make_float2(acc[ma][nb][0], acc[ma][nb][1]);
                *(float2*)&Out[(size_t)(r + 8) * N + p] =
                    make_float2(acc[ma][nb][2], acc[ma][nb][3]);
            }
        }
    }
}

// ---------------------------------------------------------------------------
// Window attention, window-native layout. Block = (window, head), 128 thr.
// Q/K/V smem [d][t]: rows 128B, 16B chunks XOR-swizzled (c ^ (d&7)).
// S=QK^T: A,B via ldmatrix.x4.trans. P smem [t][t'] swizzled. PV: plain x4.
// ---------------------------------------------------------------------------
__global__ __launch_bounds__(128) void win_attn()
{
    __shared__ uint32_t Qs[48 * 32];
    __shared__ uint32_t Ks[48 * 32];
    __shared__ uint32_t Vs[48 * 32];
    __shared__ uint32_t Ss[64 * 32];
    __shared__ __align__(16) __half Oh[48 * 72];

    const int tid  = threadIdx.x;
    const int lane = tid & 31;
    const int wid  = tid >> 5;
    const int head = blockIdx.y;
    const int b    = blockIdx.z;
    const int win  = blockIdx.x;

    const size_t base = ((size_t)b * C3 + (size_t)head * 48) * HW + (size_t)win * 64;
    const __half* qg = g_qkvh + base;
    const __half* kg = qg + (size_t)C * HW;
    const __half* vg = qg + (size_t)2 * C * HW;
    const float scale = 0.14433756729740643f;   // 48^-0.5

    // stage: 384 uint4 per tensor, fully coalesced (128B per d-row)
    #pragma unroll
    for (int it = 0; it < 3; ++it) {
        int idx = tid + it * 128;
        int d = idx >> 3, c = idx & 7;
        int dw = d * 32 + ((c ^ (d & 7)) * 4);
        *(uint4*)&Qs[dw] = *(const uint4*)(qg + (size_t)d * HW + c * 8);
        *(uint4*)&Ks[dw] = *(const uint4*)(kg + (size_t)d * HW + c * 8);
        *(uint4*)&Vs[dw] = *(const uint4*)(vg + (size_t)d * HW + c * 8);
    }
    __syncthreads();

    const int r  = lane >> 2;
    const int cq = lane & 3;
    const int row0 = wid * 16 + r;
    const uint32_t qb = smem_u32(Qs), kb = smem_u32(Ks),
                   vb = smem_u32(Vs), sb = smem_u32(Ss);

    // ---- S = Q K^T ----
    float sacc[8][4];
    #pragma unroll
    for (int nb = 0; nb < 8; ++nb)
        #pragma unroll
        for (int v = 0; v < 4; ++v) sacc[nb][v] = 0.f;

    #pragma unroll
    for (int ks = 0; ks < 3; ++ks) {
        uint32_t a[4];
        {
            int d = ks * 16 + ((lane >> 4) << 3) + (lane & 7);
            int c = wid * 2 + ((lane >> 3) & 1);
            ldsm_x4t(a[0], a[1], a[2], a[3],
                     qb + (d * 32 + ((c ^ (d & 7)) * 4)) * 4);
        }
        #pragma unroll
        for (int nbp = 0; nbp < 4; ++nbp) {
            uint32_t bb[4];
            int d = ks * 16 + (lane & 15);
            int c = nbp * 2 + (lane >> 4);
            ldsm_x4t(bb[0], bb[1], bb[2], bb[3],
                     kb + (d * 32 + ((c ^ (d & 7)) * 4)) * 4);
            mma_f16(sacc[nbp * 2],     a, &bb[0]);
            mma_f16(sacc[nbp * 2 + 1], a, &bb[2]);
        }
    }

    // ---- softmax in registers ----
    float mx0 = -1e30f, mx8 = -1e30f;
    #pragma unroll
    for (int nb = 0; nb < 8; ++nb) {
        mx0 = fmaxf(mx0, fmaxf(sacc[nb][0], sacc[nb][1]));
        mx8 = fmaxf(mx8, fmaxf(sacc[nb][2], sacc[nb][3]));
    }
    mx0 = fmaxf(mx0, __shfl_xor_sync(0xffffffffu, mx0, 1));
    mx0 = fmaxf(mx0, __shfl_xor_sync(0xffffffffu, mx0, 2));
    mx8 = fmaxf(mx8, __shfl_xor_sync(0xffffffffu, mx8, 1));
    mx8 = fmaxf(mx8, __shfl_xor_sync(0xffffffffu, mx8, 2));

    float s0 = 0.f, s8 = 0.f;
    #pragma unroll
    for (int nb = 0; nb < 8; ++nb) {
        sacc[nb][0] = __expf((sacc[nb][0] - mx0) * scale); s0 += sacc[nb][0];
        sacc[nb][1] = __expf((sacc[nb][1] - mx0) * scale); s0 += sacc[nb][1];
        sacc[nb][2] = __expf((sacc[nb][2] - mx8) * scale); s8 += sacc[nb][2];
        sacc[nb][3] = __expf((sacc[nb][3] - mx8) * scale); s8 += sacc[nb][3];
    }
    s0 += __shfl_xor_sync(0xffffffffu, s0, 1);
    s0 += __shfl_xor_sync(0xffffffffu, s0, 2);
    s8 += __shfl_xor_sync(0xffffffffu, s8, 1);
    s8 += __shfl_xor_sync(0xffffffffu, s8, 2);
    const float i0 = 1.f / s0, i8 = 1.f / s8;

    // P -> Ss (swizzled rows of 128B)
    #pragma unroll
    for (int nb = 0; nb < 8; ++nb) {
        Ss[row0 * 32 + ((nb ^ (row0 & 7)) * 4 + cq)] =
            pack_h2(sacc[nb][0] * i0, sacc[nb][1] * i0);
        Ss[(row0 + 8) * 32 + ((nb ^ ((row0 + 8) & 7)) * 4 + cq)] =
            pack_h2(sacc[nb][2] * i8, sacc[nb][3] * i8);
    }
    __syncwarp();

    // ---- O = P V ----
    float oacc[6][4];
    #pragma unroll
    for (int nb = 0; nb < 6; ++nb)
        #pragma unroll
        for (int v = 0; v < 4; ++v) oacc[nb][v] = 0.f;

    #pragma unroll
    for (int ks = 0; ks < 4; ++ks) {
        uint32_t a[4];
        {
            int t = wid * 16 + (lane & 15);
            int c = ks * 2 + (lane >> 4);
            ldsm_x4(a[0], a[1], a[2], a[3],
                    sb + (t * 32 + ((c ^ (t & 7)) * 4)) * 4);
        }
        #pragma unroll
        for (int jp = 0; jp < 3; ++jp) {
            uint32_t bb[4];
            int d = (jp * 2 + (lane >> 4)) * 8 + (lane & 7);
            int c = ks * 2 + ((lane >> 3) & 1);
            ldsm_x4(bb[0], bb[1], bb[2], bb[3],
                    vb + (d * 32 + ((c ^ (d & 7)) * 4)) * 4);
            mma_f16(oacc[jp * 2],     a, &bb[0]);
            mma_f16(oacc[jp * 2 + 1], a, &bb[2]);
        }
    }

    // O -> Oh[d][t] (smem transpose), then coalesced store
    const int t0 = row0, t8 = row0 + 8;
    #pragma unroll
    for (int nb = 0; nb < 6; ++nb) {
        int d0 = nb * 8 + 2 * cq;
        Oh[d0 * 72 + t0]       = __float2half(oacc[nb][0]);
        Oh[(d0 + 1) * 72 + t0] = __float2half(oacc[nb][1]);
        Oh[d0 * 72 + t8]       = __float2half(oacc[nb][2]);
        Oh[(d0 + 1) * 72 + t8] = __float2half(oacc[nb][3]);
    }
    __syncthreads();

    __half* og = g_attnh + ((size_t)b * C + (size_t)head * 48) * HW + (size_t)win * 64;
    #pragma unroll
    for (int it = 0; it < 3; ++it) {
        int idx = tid + it * 128;
        int d = idx >> 3, c = idx & 7;
        *(uint4*)(og + (size_t)d * HW + c * 8) = *(const uint4*)&Oh[d * 72 + c * 8];
    }
}

// ---------------------------------------------------------------------------
extern "C" void kernel_launch(void* const* d_in, const int* in_sizes, int n_in,
                              void* d_out, int out_size)
{
    const float* x     = (const float*)d_in[0];
    const float* wqkv  = (const float*)d_in[1];
    const float* wproj = (const float*)d_in[2];
    float* out = (float*)d_out;

    __half *xh, *wqkvh, *wprojh, *qkvh, *attnh;
    cudaGetSymbolAddress((void**)&xh,     g_xh);
    cudaGetSymbolAddress((void**)&wqkvh,  g_wqkvh);
    cudaGetSymbolAddress((void**)&wprojh, g_wprojh);
    cudaGetSymbolAddress((void**)&qkvh,   g_qkvh);
    cudaGetSymbolAddress((void**)&attnh,  g_attnh);

    const int smem_bytes = NSTAGE * STGB;      // 73728
    cudaFuncSetAttribute(gemm_f16<true>,  cudaFuncAttributeMaxDynamicSharedMemorySize, smem_bytes);
    cudaFuncSetAttribute(gemm_f16<false>, cudaFuncAttributeMaxDynamicSharedMemorySize, smem_bytes);

    // 0) fp32 -> fp16 conversions
    cvt_f2h<<<4096, 256>>>(x, xh, NB * C * HW / 4);
    cvt_f2h<<<256, 256>>>(wqkv, wqkvh, C3 * C / 4);
    cvt_f2h<<<128, 256>>>(wproj, wprojh, C * C / 4);

    // 1) QKV projection: pixel-layout in, window-layout out
    dim3 g1(C3 / 128, HW / 256, NB);
    gemm_f16<true><<<g1, 512, smem_bytes>>>(wqkvh, xh, qkvh, C3, C, HW);

    // 2) Window attention (window-native, fully coalesced)
    dim3 g2(1024, 8, NB);
    win_attn<<<g2, 128>>>();

    // 3) Output projection: window-layout in, pixel-layout fp32 out
    dim3 g3(C / 128, HW / 256, NB);
    gemm_f16<false><<<g3, 512, smem_bytes>>>(wprojh, attnh, out, C, C, HW);
}